// round 9
// baseline (speedup 1.0000x reference)
#include <cuda_runtime.h>
#include <cuda_bf16.h>
#include <math.h>
#include <stdint.h>

#define B_ 8
#define T_ 2048
#define D_ 1024
#define H_ 128
#define SCALE2 0.12751763226289247f   // log2(e)/sqrt(128)
#define MASKV  (-1e30f)

__device__ __forceinline__ uint32_t smem_u32(const void* p) {
    uint32_t a;
    asm("{ .reg .u64 t; cvta.to.shared.u64 t, %1; cvt.u32.u64 %0, t; }"
        : "=r"(a) : "l"(p));
    return a;
}
__device__ __forceinline__ uint32_t pack_bf(float a, float b) {
    __nv_bfloat162 t = __floats2bfloat162_rn(a, b);
    return *reinterpret_cast<uint32_t*>(&t);
}

#define CP16(dst, src) \
    asm volatile("cp.async.cg.shared.global [%0], [%1], 16;" \
                 :: "r"(dst), "l"(src) : "memory")
#define CP_COMMIT() asm volatile("cp.async.commit_group;" ::: "memory")
#define CP_WAIT0()  asm volatile("cp.async.wait_group 0;" ::: "memory")
#define CP_WAIT1()  asm volatile("cp.async.wait_group 1;" ::: "memory")

#define LDSM4(r0, r1, r2, r3, addr) \
    asm volatile("ldmatrix.sync.aligned.m8n8.x4.shared.b16 {%0,%1,%2,%3}, [%4];" \
                 : "=r"(r0), "=r"(r1), "=r"(r2), "=r"(r3) : "r"(addr))
#define LDSM4T(r0, r1, r2, r3, addr) \
    asm volatile("ldmatrix.sync.aligned.m8n8.x4.trans.shared.b16 {%0,%1,%2,%3}, [%4];" \
                 : "=r"(r0), "=r"(r1), "=r"(r2), "=r"(r3) : "r"(addr))

#define MMA16816(d, a, b) \
    asm volatile("mma.sync.aligned.m16n8k16.row.col.f32.bf16.bf16.f32 " \
                 "{%0,%1,%2,%3},{%4,%5,%6,%7},{%8,%9},{%0,%1,%2,%3};" \
                 : "+f"((d)[0]), "+f"((d)[1]), "+f"((d)[2]), "+f"((d)[3]) \
                 : "r"((a)[0]), "r"((a)[1]), "r"((a)[2]), "r"((a)[3]), \
                   "r"((b)[0]), "r"((b)[1]))

// ---- device scratch ----
__device__ __nv_bfloat16 g_q_hi[(size_t)B_ * T_ * H_];
__device__ __nv_bfloat16 g_q_lo[(size_t)B_ * T_ * H_];
__device__ __nv_bfloat16 g_k_hi[(size_t)B_ * T_ * H_];
__device__ __nv_bfloat16 g_k_lo[(size_t)B_ * T_ * H_];
__device__ __nv_bfloat16 g_v_hi[(size_t)B_ * T_ * H_];
__device__ __nv_bfloat16 g_v_lo[(size_t)B_ * T_ * H_];
__device__ __nv_bfloat16 g_Wb_hi[384 * 1024];
__device__ __nv_bfloat16 g_Wb_lo[384 * 1024];
__device__ __nv_bfloat16 g_x_hi[(size_t)B_ * T_ * D_];
__device__ __nv_bfloat16 g_x_lo[(size_t)B_ * T_ * D_];

// ---------------------------------------------------------------------------
// Prep W
// ---------------------------------------------------------------------------
__global__ __launch_bounds__(256) void prep_w_kernel(
    const float* __restrict__ Wq,
    const float* __restrict__ Wk,
    const float* __restrict__ Wv)
{
    const int n = blockIdx.x;
    const float* W = (n < 128) ? Wq : (n < 256 ? Wk : Wv);
    const int h = n & 127;
    for (int k = threadIdx.x; k < 1024; k += 256) {
        float w = W[(size_t)k * H_ + h];
        __nv_bfloat16 hi = __float2bfloat16(w);
        float lo = w - __bfloat162float(hi);
        g_Wb_hi[(size_t)n * 1024 + k] = hi;
        g_Wb_lo[(size_t)n * 1024 + k] = __float2bfloat16(lo);
    }
}

// ---------------------------------------------------------------------------
// Prep X
// ---------------------------------------------------------------------------
__global__ __launch_bounds__(256) void prep_x_kernel(const float* __restrict__ x)
{
    const size_t i = (size_t)blockIdx.x * 256 + threadIdx.x;
    float4 f = ((const float4*)x)[i];
    __nv_bfloat16 h0 = __float2bfloat16(f.x);
    __nv_bfloat16 h1 = __float2bfloat16(f.y);
    __nv_bfloat16 h2 = __float2bfloat16(f.z);
    __nv_bfloat16 h3 = __float2bfloat16(f.w);
    uint2 hv, lv;
    hv.x = (uint32_t)__bfloat16_as_ushort(h0) |
           ((uint32_t)__bfloat16_as_ushort(h1) << 16);
    hv.y = (uint32_t)__bfloat16_as_ushort(h2) |
           ((uint32_t)__bfloat16_as_ushort(h3) << 16);
    lv.x = pack_bf(f.x - __bfloat162float(h0), f.y - __bfloat162float(h1));
    lv.y = pack_bf(f.z - __bfloat162float(h2), f.w - __bfloat162float(h3));
    ((uint2*)g_x_hi)[i] = hv;
    ((uint2*)g_x_lo)[i] = lv;
}

// ---------------------------------------------------------------------------
// QKV GEMM: 512 threads, 16 warps as 4x4, warp tile 32x32 -> 4 warps/SMSP.
// cp.async double-buffered 64KB stages (same layout as before).
// ---------------------------------------------------------------------------
#define QSTAGE 65536
#define QK_SMEM 131072

__device__ __forceinline__ void qkv_issue(uint32_t dstbase, int m0, int n0,
                                          int k0, int tid)
{
#pragma unroll
    for (int i = 0; i < 2; i++) {
        int idx = i * 512 + tid;
        int r = idx >> 3, g = idx & 7;
        uint32_t off = (uint32_t)(r * 128 + ((g ^ (r & 7)) << 4));
        const size_t ax = (size_t)(m0 + r) * D_ + k0 + g * 8;
        const size_t bx = (size_t)(n0 + r) * D_ + k0 + g * 8;
        CP16(dstbase + off,         g_x_hi + ax);
        CP16(dstbase + 16384 + off, g_x_lo + ax);
        CP16(dstbase + 32768 + off, g_Wb_hi + bx);
        CP16(dstbase + 49152 + off, g_Wb_lo + bx);
    }
}

__global__ __launch_bounds__(512, 1) void qkv_mma_kernel()
{
    extern __shared__ char smq[];
    const uint32_t sb = smem_u32(smq);
    const int tid  = threadIdx.x;
    const int lane = tid & 31, warp = tid >> 5;
    const int wm = warp >> 2, wn = warp & 3;
    const int m0 = blockIdx.x * 128;
    const int n0 = blockIdx.y * 128;

    float acc[2][4][4];
#pragma unroll
    for (int mt = 0; mt < 2; mt++)
#pragma unroll
        for (int nt = 0; nt < 4; nt++)
#pragma unroll
            for (int j = 0; j < 4; j++) acc[mt][nt][j] = 0.f;

    uint32_t a_rb[2], a_xr[2];
#pragma unroll
    for (int mt = 0; mt < 2; mt++) {
        int rowA = wm * 32 + mt * 16 + (lane & 15);
        a_rb[mt] = (uint32_t)(rowA * 128);
        a_xr[mt] = (uint32_t)((rowA & 7) << 4);
    }
    const uint32_t a_cb = (uint32_t)((lane >> 4) * 16);
    uint32_t b_rb[2], b_xr[2];
#pragma unroll
    for (int p = 0; p < 2; p++) {
        int nB = wn * 32 + p * 16 + ((lane >> 4) << 3) + (lane & 7);
        b_rb[p] = (uint32_t)(nB * 128);
        b_xr[p] = (uint32_t)((nB & 7) << 4);
    }
    const uint32_t b_cb = (uint32_t)(((lane >> 3) & 1) * 16);

    qkv_issue(sb, m0, n0, 0, tid);
    CP_COMMIT();

    for (int kc = 0; kc < 16; kc++) {
        if (kc < 15) {
            qkv_issue(sb + (uint32_t)(((kc + 1) & 1) * QSTAGE),
                      m0, n0, (kc + 1) * 64, tid);
            CP_COMMIT();
            CP_WAIT1();
        } else {
            CP_WAIT0();
        }
        __syncthreads();

        const uint32_t bufb = sb + (uint32_t)((kc & 1) * QSTAGE);
#pragma unroll
        for (int ks = 0; ks < 4; ks++) {
            const uint32_t acol = (a_cb + ks * 32);
            const uint32_t bcol = (b_cb + ks * 32);
            uint32_t ah[2][4], al[2][4];
#pragma unroll
            for (int mt = 0; mt < 2; mt++) {
                LDSM4(ah[mt][0], ah[mt][1], ah[mt][2], ah[mt][3],
                      bufb + a_rb[mt] + (acol ^ a_xr[mt]));
                LDSM4(al[mt][0], al[mt][1], al[mt][2], al[mt][3],
                      bufb + 16384 + a_rb[mt] + (acol ^ a_xr[mt]));
            }
            uint32_t bh[4][2], bl[4][2];
#pragma unroll
            for (int p = 0; p < 2; p++) {
                uint32_t r0, r1, r2, r3;
                LDSM4(r0, r1, r2, r3, bufb + 32768 + b_rb[p] + (bcol ^ b_xr[p]));
                bh[2 * p][0] = r0; bh[2 * p][1] = r1;
                bh[2 * p + 1][0] = r2; bh[2 * p + 1][1] = r3;
                LDSM4(r0, r1, r2, r3, bufb + 49152 + b_rb[p] + (bcol ^ b_xr[p]));
                bl[2 * p][0] = r0; bl[2 * p][1] = r1;
                bl[2 * p + 1][0] = r2; bl[2 * p + 1][1] = r3;
            }
#pragma unroll
            for (int mt = 0; mt < 2; mt++)
#pragma unroll
                for (int nt = 0; nt < 4; nt++) {
                    MMA16816(acc[mt][nt], ah[mt], bh[nt]);
                    MMA16816(acc[mt][nt], ah[mt], bl[nt]);
                    MMA16816(acc[mt][nt], al[mt], bh[nt]);
                }
        }
        __syncthreads();
    }

    __nv_bfloat16* oh = (blockIdx.y == 0) ? g_q_hi : (blockIdx.y == 1 ? g_k_hi : g_v_hi);
    __nv_bfloat16* ol = (blockIdx.y == 0) ? g_q_lo : (blockIdx.y == 1 ? g_k_lo : g_v_lo);
    const int g = lane >> 2, tig = lane & 3;
#pragma unroll
    for (int mt = 0; mt < 2; mt++) {
        const int row0 = m0 + wm * 32 + mt * 16 + g;
#pragma unroll
        for (int nt = 0; nt < 4; nt++) {
            const int col = wn * 32 + nt * 8 + tig * 2;
#pragma unroll
            for (int h = 0; h < 2; h++) {
                const int row = row0 + h * 8;
                float a0 = acc[mt][nt][2 * h], a1 = acc[mt][nt][2 * h + 1];
                __nv_bfloat16 h0 = __float2bfloat16(a0);
                __nv_bfloat16 h1 = __float2bfloat16(a1);
                *(uint32_t*)(oh + (size_t)row * H_ + col) =
                    (uint32_t)__bfloat16_as_ushort(h0) |
                    ((uint32_t)__bfloat16_as_ushort(h1) << 16);
                *(uint32_t*)(ol + (size_t)row * H_ + col) =
                    pack_bf(a0 - __bfloat162float(h0), a1 - __bfloat162float(h1));
            }
        }
    }
}

// ---------------------------------------------------------------------------
// Flash attention: 256 threads, 8 warps = 4 row-groups x 2 col-halves.
// exp2-domain softmax with ONE stat-exchange barrier per k-tile:
// exponentiate vs local max immediately; publish (max,sum); rescale P in pack.
// ---------------------------------------------------------------------------
#define AQH 0
#define AQL 16384
#define AKV0 32768
#define KVBUF 65536
#define AEXM 163840
#define AEXS 164352
#define ATT_SMEM 164864

__device__ __forceinline__ void kv_issue256(uint32_t dstbase, size_t kbase, int tid)
{
#pragma unroll
    for (int i = 0; i < 4; i++) {
        int idx = i * 256 + tid;
        int r = idx >> 4, gq = idx & 15;
        uint32_t off = (uint32_t)(r * 256 + ((gq ^ (r & 7)) << 4));
        const size_t ge = kbase + (size_t)r * 128 + gq * 8;
        CP16(dstbase + off,         g_k_hi + ge);
        CP16(dstbase + 16384 + off, g_k_lo + ge);
        CP16(dstbase + 32768 + off, g_v_hi + ge);
        CP16(dstbase + 49152 + off, g_v_lo + ge);
    }
}

__global__ __launch_bounds__(256, 1) void attn_mma_kernel(float* __restrict__ out)
{
    extern __shared__ char smA[];
    const uint32_t sb = smem_u32(smA);
    float* mPart = (float*)(smA + AEXM);   // [2][64]
    float* sPart = (float*)(smA + AEXS);   // [2][64]

    const int tid  = threadIdx.x;
    const int lane = tid & 31, warp = tid >> 5;
    const int wr = warp & 3;
    const int wh = warp >> 2;
    const int b    = blockIdx.y;
    const int g4   = lane >> 2, tig = lane & 3;
    const int b3   = (lane >> 3) & 1;
    const int rk   = ((lane >> 4) << 3) + (lane & 7);
    const int xr7  = lane & 7;

    for (int pass = 0; pass < 2; pass++) {
        const int qt = pass ? (31 - (int)blockIdx.x) : (int)blockIdx.x;
        const size_t qbase = ((size_t)b * T_ + (size_t)qt * 64) * H_;
        const size_t batchbase = (size_t)b * T_ * H_;

        __syncthreads();
        kv_issue256(sb + AKV0, batchbase, tid);
        CP_COMMIT();

#pragma unroll
        for (int i = 0; i < 4; i++) {
            int idx = i * 256 + tid;
            int r = idx >> 4, gq = idx & 15;
            uint32_t off = (uint32_t)(r * 256 + ((gq ^ (r & 7)) << 4));
            *(uint4*)(smA + AQH + off) = *(const uint4*)(g_q_hi + qbase + r * 128 + gq * 8);
            *(uint4*)(smA + AQL + off) = *(const uint4*)(g_q_lo + qbase + r * 128 + gq * 8);
        }
        __syncthreads();

        uint32_t qh[8][4], ql[8][4];
        {
            const int r = wr * 16 + (lane & 15);
#pragma unroll
            for (int ks = 0; ks < 8; ks++) {
                int gq = ks * 2 + (lane >> 4);
                uint32_t off = (uint32_t)(r * 256 + ((gq ^ (r & 7)) << 4));
                LDSM4(qh[ks][0], qh[ks][1], qh[ks][2], qh[ks][3], sb + AQH + off);
                LDSM4(ql[ks][0], ql[ks][1], ql[ks][2], ql[ks][3], sb + AQL + off);
            }
        }

        float oacc[16][4];
#pragma unroll
        for (int t = 0; t < 16; t++)
#pragma unroll
            for (int j = 0; j < 4; j++) oacc[t][j] = 0.f;
        float m0 = MASKV, m1 = MASKV, l0 = 0.f, l1 = 0.f;

        const int r0 = wr * 16 + g4, r1 = r0 + 8;

        for (int kt = 0; kt <= qt; kt++) {
            if (kt < qt) {
                kv_issue256(sb + AKV0 + (uint32_t)(((kt + 1) & 1) * KVBUF),
                            batchbase + (size_t)(kt + 1) * 64 * H_, tid);
                CP_COMMIT();
                CP_WAIT1();
            } else {
                CP_WAIT0();
            }
            __syncthreads();
            const uint32_t kvb = sb + AKV0 + (uint32_t)((kt & 1) * KVBUF);

            // ---- S = Q K^T for this warp's 32 cols (3-term) ----
            float sacc[4][4];
#pragma unroll
            for (int nt = 0; nt < 4; nt++)
#pragma unroll
                for (int j = 0; j < 4; j++) sacc[nt][j] = 0.f;

#pragma unroll
            for (int ks = 0; ks < 8; ks++) {
                const int gq = ks * 2 + b3;
                const uint32_t csw = (uint32_t)((gq ^ xr7) << 4);
#pragma unroll
                for (int p = 0; p < 2; p++) {
                    const uint32_t off =
                        (uint32_t)((wh * 32 + p * 16 + rk) * 256) + csw;
                    uint32_t h0, h1, h2, h3, u0, u1, u2, u3;
                    LDSM4(h0, h1, h2, h3, kvb + off);
                    LDSM4(u0, u1, u2, u3, kvb + 16384 + off);
                    uint32_t bh0[2] = {h0, h1}, bh1[2] = {h2, h3};
                    uint32_t bl0[2] = {u0, u1}, bl1[2] = {u2, u3};
                    MMA16816(sacc[2 * p],     qh[ks], bh0);
                    MMA16816(sacc[2 * p],     qh[ks], bl0);
                    MMA16816(sacc[2 * p],     ql[ks], bh0);
                    MMA16816(sacc[2 * p + 1], qh[ks], bh1);
                    MMA16816(sacc[2 * p + 1], qh[ks], bl1);
                    MMA16816(sacc[2 * p + 1], ql[ks], bh1);
                }
            }

            // ---- exp2-domain scale + causal mask ----
#pragma unroll
            for (int nt = 0; nt < 4; nt++)
#pragma unroll
                for (int j = 0; j < 4; j++) sacc[nt][j] *= SCALE2;
            if (kt == qt) {
#pragma unroll
                for (int nt = 0; nt < 4; nt++) {
                    const int c0 = wh * 32 + nt * 8 + tig * 2, c1 = c0 + 1;
                    if (c0 > r0) sacc[nt][0] = MASKV;
                    if (c1 > r0) sacc[nt][1] = MASKV;
                    if (c0 > r1) sacc[nt][2] = MASKV;
                    if (c1 > r1) sacc[nt][3] = MASKV;
                }
            }

            // ---- local max (this half's 32 cols) ----
            float rm0 = MASKV, rm1 = MASKV;
#pragma unroll
            for (int nt = 0; nt < 4; nt++) {
                rm0 = fmaxf(rm0, fmaxf(sacc[nt][0], sacc[nt][1]));
                rm1 = fmaxf(rm1, fmaxf(sacc[nt][2], sacc[nt][3]));
            }
            rm0 = fmaxf(rm0, __shfl_xor_sync(0xffffffffu, rm0, 1));
            rm0 = fmaxf(rm0, __shfl_xor_sync(0xffffffffu, rm0, 2));
            rm1 = fmaxf(rm1, __shfl_xor_sync(0xffffffffu, rm1, 1));
            rm1 = fmaxf(rm1, __shfl_xor_sync(0xffffffffu, rm1, 2));
            if (tig == 0) {
                mPart[wh * 64 + r0] = rm0;
                mPart[wh * 64 + r1] = rm1;
            }

            // ---- exponentiate vs LOCAL max immediately ----
            float rs0 = 0.f, rs1 = 0.f;
#pragma unroll
            for (int nt = 0; nt < 4; nt++) {
                float p0 = exp2f(sacc[nt][0] - rm0);
                float p1 = exp2f(sacc[nt][1] - rm0);
                float p2 = exp2f(sacc[nt][2] - rm1);
                float p3 = exp2f(sacc[nt][3] - rm1);
                sacc[nt][0] = p0; sacc[nt][1] = p1;
                sacc[nt][2] = p2; sacc[nt][3] = p3;
                rs0 += p0 + p1; rs1 += p2 + p3;
            }
            rs0 += __shfl_xor_sync(0xffffffffu, rs0, 1);
            rs0 += __shfl_xor_sync(0xffffffffu, rs0, 2);
            rs1 += __shfl_xor_sync(0xffffffffu, rs1, 1);
            rs1 += __shfl_xor_sync(0xffffffffu, rs1, 2);
            if (tig == 0) {
                sPart[wh * 64 + r0] = rs0;
                sPart[wh * 64 + r1] = rs1;
            }
            __syncthreads();          // ONE exchange barrier

            const float rmA0 = mPart[r0], rmB0 = mPart[64 + r0];
            const float rmA1 = mPart[r1], rmB1 = mPart[64 + r1];
            const float mn0 = fmaxf(m0, fmaxf(rmA0, rmB0));
            const float mn1 = fmaxf(m1, fmaxf(rmA1, rmB1));
            const float corr0 = exp2f(m0 - mn0), corr1 = exp2f(m1 - mn1);
            l0 = l0 * corr0 + sPart[r0]      * exp2f(rmA0 - mn0)
                            + sPart[64 + r0] * exp2f(rmB0 - mn0);
            l1 = l1 * corr1 + sPart[r1]      * exp2f(rmA1 - mn1)
                            + sPart[64 + r1] * exp2f(rmB1 - mn1);
            m0 = mn0; m1 = mn1;
            const float fac0 = exp2f(rm0 - mn0);   // local->global rescale
            const float fac1 = exp2f(rm1 - mn1);

#pragma unroll
            for (int t = 0; t < 16; t++) {
                oacc[t][0] *= corr0; oacc[t][1] *= corr0;
                oacc[t][2] *= corr1; oacc[t][3] *= corr1;
            }

            // ---- P fragments in-register (rescale folded into pack) ----
            uint32_t ph[2][4], pl[2][4];
#pragma unroll
            for (int c = 0; c < 2; c++) {
#pragma unroll
                for (int half = 0; half < 2; half++) {
                    const int nt = 2 * c + half;
                    float a0 = sacc[nt][0] * fac0, a1 = sacc[nt][1] * fac0;
                    float a2 = sacc[nt][2] * fac1, a3 = sacc[nt][3] * fac1;
                    __nv_bfloat16 h0 = __float2bfloat16(a0);
                    __nv_bfloat16 h1 = __float2bfloat16(a1);
                    __nv_bfloat16 h2 = __float2bfloat16(a2);
                    __nv_bfloat16 h3 = __float2bfloat16(a3);
                    ph[c][2 * half] =
                        (uint32_t)__bfloat16_as_ushort(h0) |
                        ((uint32_t)__bfloat16_as_ushort(h1) << 16);
                    ph[c][2 * half + 1] =
                        (uint32_t)__bfloat16_as_ushort(h2) |
                        ((uint32_t)__bfloat16_as_ushort(h3) << 16);
                    pl[c][2 * half] =
                        pack_bf(a0 - __bfloat162float(h0), a1 - __bfloat162float(h1));
                    pl[c][2 * half + 1] =
                        pack_bf(a2 - __bfloat162float(h2), a3 - __bfloat162float(h3));
                }
            }

            // ---- O += P V over this warp's 32 P-cols (3-term) ----
#pragma unroll
            for (int c = 0; c < 2; c++) {
                const uint32_t roff = (uint32_t)(((wh * 2 + c) * 16 + rk) * 256);
#pragma unroll
                for (int jp = 0; jp < 8; jp++) {
                    const int gq = jp * 2 + b3;
                    const uint32_t off = roff + (uint32_t)((gq ^ xr7) << 4);
                    uint32_t t0, t1, t2, t3, u0, u1, u2, u3;
                    LDSM4T(t0, t1, t2, t3, kvb + 32768 + off);
                    LDSM4T(u0, u1, u2, u3, kvb + 49152 + off);
                    uint32_t vh0[2] = {t0, t2}, vh1[2] = {t1, t3};
                    uint32_t vl0[2] = {u0, u2}, vl1[2] = {u1, u3};
                    MMA16816(oacc[2 * jp],     ph[c], vh0);
                    MMA16816(oacc[2 * jp],     ph[c], vl0);
                    MMA16816(oacc[2 * jp],     pl[c], vh0);
                    MMA16816(oacc[2 * jp + 1], ph[c], vh1);
                    MMA16816(oacc[2 * jp + 1], ph[c], vl1);
                    MMA16816(oacc[2 * jp + 1], pl[c], vh1);
                }
            }
            __syncthreads();
        }

        // ---- merge partial O between col-half partners, then store ----
        __syncthreads();
        if (wh == 1) {
            float* buf = (float*)(smA + AKV0 + wr * 8192);
#pragma unroll
            for (int t = 0; t < 16; t++) {
                const int col = t * 8 + tig * 2;
                *(float2*)&buf[g4 * 128 + col] =
                    make_float2(oacc[t][0], oacc[t][1]);
                *(float2*)&buf[(g4 + 8) * 128 + col] =
                    make_float2(oacc[t][2], oacc[t][3]);
            }
        }
        __syncthreads();
        if (wh == 0) {
            const float* buf = (const float*)(smA + AKV0 + wr * 8192);
            const float inv0 = 1.f / l0, inv1 = 1.f / l1;
#pragma unroll
            for (int t = 0; t < 16; t++) {
                const int col = t * 8 + tig * 2;
                float2 p0 = *(const float2*)&buf[g4 * 128 + col];
                float2 p1 = *(const float2*)&buf[(g4 + 8) * 128 + col];
                *(float2*)(out + qbase + (size_t)r0 * H_ + col) =
                    make_float2((oacc[t][0] + p0.x) * inv0,
                                (oacc[t][1] + p0.y) * inv0);
                *(float2*)(out + qbase + (size_t)r1 * H_ + col) =
                    make_float2((oacc[t][2] + p1.x) * inv1,
                                (oacc[t][3] + p1.y) * inv1);
            }
        }
    }
}

// ---------------------------------------------------------------------------
extern "C" void kernel_launch(void* const* d_in, const int* in_sizes, int n_in,
                              void* d_out, int out_size)
{
    const float* x  = (const float*)d_in[0];
    const float* Wq = (const float*)d_in[1];
    const float* Wk = (const float*)d_in[2];
    const float* Wv = (const float*)d_in[3];
    float* out = (float*)d_out;

    prep_w_kernel<<<384, 256>>>(Wq, Wk, Wv);
    prep_x_kernel<<<16384, 256>>>(x);

    cudaFuncSetAttribute(qkv_mma_kernel,
                         cudaFuncAttributeMaxDynamicSharedMemorySize, QK_SMEM);
    qkv_mma_kernel<<<dim3(128, 3), 512, QK_SMEM>>>();

    cudaFuncSetAttribute(attn_mma_kernel,
                         cudaFuncAttributeMaxDynamicSharedMemorySize, ATT_SMEM);
    attn_mma_kernel<<<dim3(16, 8), 256, ATT_SMEM>>>(out);
}

// round 10
// speedup vs baseline: 1.0461x; 1.0461x over previous
#include <cuda_runtime.h>
#include <cuda_bf16.h>
#include <math.h>
#include <stdint.h>

#define B_ 8
#define T_ 2048
#define D_ 1024
#define H_ 128
#define SCALE2 0.12751763226289247f   // log2(e)/sqrt(128)
#define MASKV  (-1e30f)

__device__ __forceinline__ uint32_t smem_u32(const void* p) {
    uint32_t a;
    asm("{ .reg .u64 t; cvta.to.shared.u64 t, %1; cvt.u32.u64 %0, t; }"
        : "=r"(a) : "l"(p));
    return a;
}
__device__ __forceinline__ uint32_t pack_bf(float a, float b) {
    __nv_bfloat162 t = __floats2bfloat162_rn(a, b);
    return *reinterpret_cast<uint32_t*>(&t);
}

#define CP16(dst, src) \
    asm volatile("cp.async.cg.shared.global [%0], [%1], 16;" \
                 :: "r"(dst), "l"(src) : "memory")
#define CP_COMMIT() asm volatile("cp.async.commit_group;" ::: "memory")
#define CP_WAIT0()  asm volatile("cp.async.wait_group 0;" ::: "memory")
#define CP_WAIT1()  asm volatile("cp.async.wait_group 1;" ::: "memory")

#define LDSM4(r0, r1, r2, r3, addr) \
    asm volatile("ldmatrix.sync.aligned.m8n8.x4.shared.b16 {%0,%1,%2,%3}, [%4];" \
                 : "=r"(r0), "=r"(r1), "=r"(r2), "=r"(r3) : "r"(addr))
#define LDSM4T(r0, r1, r2, r3, addr) \
    asm volatile("ldmatrix.sync.aligned.m8n8.x4.trans.shared.b16 {%0,%1,%2,%3}, [%4];" \
                 : "=r"(r0), "=r"(r1), "=r"(r2), "=r"(r3) : "r"(addr))

#define MMA16816(d, a, b) \
    asm volatile("mma.sync.aligned.m16n8k16.row.col.f32.bf16.bf16.f32 " \
                 "{%0,%1,%2,%3},{%4,%5,%6,%7},{%8,%9},{%0,%1,%2,%3};" \
                 : "+f"((d)[0]), "+f"((d)[1]), "+f"((d)[2]), "+f"((d)[3]) \
                 : "r"((a)[0]), "r"((a)[1]), "r"((a)[2]), "r"((a)[3]), \
                   "r"((b)[0]), "r"((b)[1]))

// ---- device scratch ----
__device__ __nv_bfloat16 g_q_hi[(size_t)B_ * T_ * H_];
__device__ __nv_bfloat16 g_q_lo[(size_t)B_ * T_ * H_];
__device__ __nv_bfloat16 g_k_hi[(size_t)B_ * T_ * H_];
__device__ __nv_bfloat16 g_k_lo[(size_t)B_ * T_ * H_];
__device__ __nv_bfloat16 g_v_hi[(size_t)B_ * T_ * H_];
__device__ __nv_bfloat16 g_v_lo[(size_t)B_ * T_ * H_];
__device__ __nv_bfloat16 g_Wb_hi[384 * 1024];
__device__ __nv_bfloat16 g_Wb_lo[384 * 1024];
__device__ __nv_bfloat16 g_x_hi[(size_t)B_ * T_ * D_];
__device__ __nv_bfloat16 g_x_lo[(size_t)B_ * T_ * D_];

// ---------------------------------------------------------------------------
// Fused prep: blocks [0,16384) convert X; blocks [16384,16768) convert Wcat.
// ---------------------------------------------------------------------------
__global__ __launch_bounds__(256) void prep_kernel(
    const float* __restrict__ x,
    const float* __restrict__ Wq,
    const float* __restrict__ Wk,
    const float* __restrict__ Wv)
{
    if (blockIdx.x < 16384) {
        const size_t i = (size_t)blockIdx.x * 256 + threadIdx.x;
        float4 f = ((const float4*)x)[i];
        __nv_bfloat16 h0 = __float2bfloat16(f.x);
        __nv_bfloat16 h1 = __float2bfloat16(f.y);
        __nv_bfloat16 h2 = __float2bfloat16(f.z);
        __nv_bfloat16 h3 = __float2bfloat16(f.w);
        uint2 hv, lv;
        hv.x = (uint32_t)__bfloat16_as_ushort(h0) |
               ((uint32_t)__bfloat16_as_ushort(h1) << 16);
        hv.y = (uint32_t)__bfloat16_as_ushort(h2) |
               ((uint32_t)__bfloat16_as_ushort(h3) << 16);
        lv.x = pack_bf(f.x - __bfloat162float(h0), f.y - __bfloat162float(h1));
        lv.y = pack_bf(f.z - __bfloat162float(h2), f.w - __bfloat162float(h3));
        ((uint2*)g_x_hi)[i] = hv;
        ((uint2*)g_x_lo)[i] = lv;
    } else {
        const int n = blockIdx.x - 16384;
        const float* W = (n < 128) ? Wq : (n < 256 ? Wk : Wv);
        const int h = n & 127;
        for (int k = threadIdx.x; k < 1024; k += 256) {
            float w = W[(size_t)k * H_ + h];
            __nv_bfloat16 hi = __float2bfloat16(w);
            float lo = w - __bfloat162float(hi);
            g_Wb_hi[(size_t)n * 1024 + k] = hi;
            g_Wb_lo[(size_t)n * 1024 + k] = __float2bfloat16(lo);
        }
    }
}

// ---------------------------------------------------------------------------
// QKV GEMM: R8 version. 256 threads, 8 warps 2x4, warp tile 64x32.
// cp.async double-buffered 64KB stages.
// ---------------------------------------------------------------------------
#define QSTAGE 65536
#define QK_SMEM 131072

__device__ __forceinline__ void qkv_issue(uint32_t dstbase, int m0, int n0,
                                          int k0, int tid)
{
#pragma unroll
    for (int i = 0; i < 4; i++) {
        int idx = i * 256 + tid;
        int r = idx >> 3, g = idx & 7;
        uint32_t off = (uint32_t)(r * 128 + ((g ^ (r & 7)) << 4));
        const size_t ax = (size_t)(m0 + r) * D_ + k0 + g * 8;
        const size_t bx = (size_t)(n0 + r) * D_ + k0 + g * 8;
        CP16(dstbase + off,         g_x_hi + ax);
        CP16(dstbase + 16384 + off, g_x_lo + ax);
        CP16(dstbase + 32768 + off, g_Wb_hi + bx);
        CP16(dstbase + 49152 + off, g_Wb_lo + bx);
    }
}

__global__ __launch_bounds__(256, 1) void qkv_mma_kernel()
{
    extern __shared__ char smq[];
    const uint32_t sb = smem_u32(smq);
    const int tid  = threadIdx.x;
    const int lane = tid & 31, warp = tid >> 5;
    const int wm = warp >> 2, wn = warp & 3;
    const int m0 = blockIdx.x * 128;
    const int n0 = blockIdx.y * 128;

    float acc[4][4][4];
#pragma unroll
    for (int mt = 0; mt < 4; mt++)
#pragma unroll
        for (int nt = 0; nt < 4; nt++)
#pragma unroll
            for (int j = 0; j < 4; j++) acc[mt][nt][j] = 0.f;

    uint32_t a_rb[4], a_xr[4];
#pragma unroll
    for (int mt = 0; mt < 4; mt++) {
        int rowA = wm * 64 + mt * 16 + (lane & 15);
        a_rb[mt] = (uint32_t)(rowA * 128);
        a_xr[mt] = (uint32_t)((rowA & 7) << 4);
    }
    const uint32_t a_cb = (uint32_t)((lane >> 4) * 16);
    uint32_t b_rb[2], b_xr[2];
#pragma unroll
    for (int p = 0; p < 2; p++) {
        int nB = wn * 32 + p * 16 + ((lane >> 4) << 3) + (lane & 7);
        b_rb[p] = (uint32_t)(nB * 128);
        b_xr[p] = (uint32_t)((nB & 7) << 4);
    }
    const uint32_t b_cb = (uint32_t)(((lane >> 3) & 1) * 16);

    qkv_issue(sb, m0, n0, 0, tid);
    CP_COMMIT();

    for (int kc = 0; kc < 16; kc++) {
        if (kc < 15) {
            qkv_issue(sb + (uint32_t)(((kc + 1) & 1) * QSTAGE),
                      m0, n0, (kc + 1) * 64, tid);
            CP_COMMIT();
            CP_WAIT1();
        } else {
            CP_WAIT0();
        }
        __syncthreads();

        const uint32_t bufb = sb + (uint32_t)((kc & 1) * QSTAGE);
#pragma unroll
        for (int ks = 0; ks < 4; ks++) {
            const uint32_t acol = (a_cb + ks * 32);
            const uint32_t bcol = (b_cb + ks * 32);
            uint32_t ah[4][4], al[4][4];
#pragma unroll
            for (int mt = 0; mt < 4; mt++) {
                LDSM4(ah[mt][0], ah[mt][1], ah[mt][2], ah[mt][3],
                      bufb + a_rb[mt] + (acol ^ a_xr[mt]));
                LDSM4(al[mt][0], al[mt][1], al[mt][2], al[mt][3],
                      bufb + 16384 + a_rb[mt] + (acol ^ a_xr[mt]));
            }
            uint32_t bh[4][2], bl[4][2];
#pragma unroll
            for (int p = 0; p < 2; p++) {
                uint32_t r0, r1, r2, r3;
                LDSM4(r0, r1, r2, r3, bufb + 32768 + b_rb[p] + (bcol ^ b_xr[p]));
                bh[2 * p][0] = r0; bh[2 * p][1] = r1;
                bh[2 * p + 1][0] = r2; bh[2 * p + 1][1] = r3;
                LDSM4(r0, r1, r2, r3, bufb + 49152 + b_rb[p] + (bcol ^ b_xr[p]));
                bl[2 * p][0] = r0; bl[2 * p][1] = r1;
                bl[2 * p + 1][0] = r2; bl[2 * p + 1][1] = r3;
            }
#pragma unroll
            for (int mt = 0; mt < 4; mt++)
#pragma unroll
                for (int nt = 0; nt < 4; nt++) {
                    MMA16816(acc[mt][nt], ah[mt], bh[nt]);
                    MMA16816(acc[mt][nt], ah[mt], bl[nt]);
                    MMA16816(acc[mt][nt], al[mt], bh[nt]);
                }
        }
        __syncthreads();
    }

    __nv_bfloat16* oh = (blockIdx.y == 0) ? g_q_hi : (blockIdx.y == 1 ? g_k_hi : g_v_hi);
    __nv_bfloat16* ol = (blockIdx.y == 0) ? g_q_lo : (blockIdx.y == 1 ? g_k_lo : g_v_lo);
    const int g = lane >> 2, tig = lane & 3;
#pragma unroll
    for (int mt = 0; mt < 4; mt++) {
        const int row0 = m0 + wm * 64 + mt * 16 + g;
#pragma unroll
        for (int nt = 0; nt < 4; nt++) {
            const int col = wn * 32 + nt * 8 + tig * 2;
#pragma unroll
            for (int h = 0; h < 2; h++) {
                const int row = row0 + h * 8;
                float a0 = acc[mt][nt][2 * h], a1 = acc[mt][nt][2 * h + 1];
                __nv_bfloat16 h0 = __float2bfloat16(a0);
                __nv_bfloat16 h1 = __float2bfloat16(a1);
                *(uint32_t*)(oh + (size_t)row * H_ + col) =
                    (uint32_t)__bfloat16_as_ushort(h0) |
                    ((uint32_t)__bfloat16_as_ushort(h1) << 16);
                *(uint32_t*)(ol + (size_t)row * H_ + col) =
                    pack_bf(a0 - __bfloat162float(h0), a1 - __bfloat162float(h1));
            }
        }
    }
}

// ---------------------------------------------------------------------------
// Flash attention: 256 threads, 8 warps = 4 row-groups x 2 col-halves.
// exp2 single-barrier softmax. Q fragments reloaded from smem per k-tile
// (frees 64 regs -> no spills).
// ---------------------------------------------------------------------------
#define AQH 0
#define AQL 16384
#define AKV0 32768
#define KVBUF 65536
#define AEXM 163840
#define AEXS 164352
#define ATT_SMEM 164864

__device__ __forceinline__ void kv_issue256(uint32_t dstbase, size_t kbase, int tid)
{
#pragma unroll
    for (int i = 0; i < 4; i++) {
        int idx = i * 256 + tid;
        int r = idx >> 4, gq = idx & 15;
        uint32_t off = (uint32_t)(r * 256 + ((gq ^ (r & 7)) << 4));
        const size_t ge = kbase + (size_t)r * 128 + gq * 8;
        CP16(dstbase + off,         g_k_hi + ge);
        CP16(dstbase + 16384 + off, g_k_lo + ge);
        CP16(dstbase + 32768 + off, g_v_hi + ge);
        CP16(dstbase + 49152 + off, g_v_lo + ge);
    }
}

__global__ __launch_bounds__(256, 1) void attn_mma_kernel(float* __restrict__ out)
{
    extern __shared__ char smA[];
    const uint32_t sb = smem_u32(smA);
    float* mPart = (float*)(smA + AEXM);
    float* sPart = (float*)(smA + AEXS);

    const int tid  = threadIdx.x;
    const int lane = tid & 31, warp = tid >> 5;
    const int wr = warp & 3;
    const int wh = warp >> 2;
    const int b    = blockIdx.y;
    const int g4   = lane >> 2, tig = lane & 3;
    const int b3   = (lane >> 3) & 1;
    const int rk   = ((lane >> 4) << 3) + (lane & 7);
    const int xr7  = lane & 7;

    // Q ldsm address precompute (row fixed per warp)
    const int qrow = wr * 16 + (lane & 15);
    const uint32_t q_rb = (uint32_t)(qrow * 256);
    const uint32_t q_xr = (uint32_t)((qrow & 7));

    for (int pass = 0; pass < 2; pass++) {
        const int qt = pass ? (31 - (int)blockIdx.x) : (int)blockIdx.x;
        const size_t qbase = ((size_t)b * T_ + (size_t)qt * 64) * H_;
        const size_t batchbase = (size_t)b * T_ * H_;

        __syncthreads();
        kv_issue256(sb + AKV0, batchbase, tid);
        CP_COMMIT();

#pragma unroll
        for (int i = 0; i < 4; i++) {
            int idx = i * 256 + tid;
            int r = idx >> 4, gq = idx & 15;
            uint32_t off = (uint32_t)(r * 256 + ((gq ^ (r & 7)) << 4));
            *(uint4*)(smA + AQH + off) = *(const uint4*)(g_q_hi + qbase + r * 128 + gq * 8);
            *(uint4*)(smA + AQL + off) = *(const uint4*)(g_q_lo + qbase + r * 128 + gq * 8);
        }

        float oacc[16][4];
#pragma unroll
        for (int t = 0; t < 16; t++)
#pragma unroll
            for (int j = 0; j < 4; j++) oacc[t][j] = 0.f;
        float m0 = MASKV, m1 = MASKV, l0 = 0.f, l1 = 0.f;

        const int r0 = wr * 16 + g4, r1 = r0 + 8;

        for (int kt = 0; kt <= qt; kt++) {
            if (kt < qt) {
                kv_issue256(sb + AKV0 + (uint32_t)(((kt + 1) & 1) * KVBUF),
                            batchbase + (size_t)(kt + 1) * 64 * H_, tid);
                CP_COMMIT();
                CP_WAIT1();
            } else {
                CP_WAIT0();
            }
            __syncthreads();
            const uint32_t kvb = sb + AKV0 + (uint32_t)((kt & 1) * KVBUF);

            // ---- S = Q K^T for this warp's 32 cols (3-term) ----
            float sacc[4][4];
#pragma unroll
            for (int nt = 0; nt < 4; nt++)
#pragma unroll
                for (int j = 0; j < 4; j++) sacc[nt][j] = 0.f;

#pragma unroll
            for (int ks = 0; ks < 8; ks++) {
                // reload Q fragments for this ks from smem
                uint32_t qh[4], ql[4];
                {
                    int gq = ks * 2 + (lane >> 4);
                    uint32_t off = q_rb + (uint32_t)((gq ^ q_xr) << 4);
                    LDSM4(qh[0], qh[1], qh[2], qh[3], sb + AQH + off);
                    LDSM4(ql[0], ql[1], ql[2], ql[3], sb + AQL + off);
                }
                const int gq = ks * 2 + b3;
                const uint32_t csw = (uint32_t)((gq ^ xr7) << 4);
#pragma unroll
                for (int p = 0; p < 2; p++) {
                    const uint32_t off =
                        (uint32_t)((wh * 32 + p * 16 + rk) * 256) + csw;
                    uint32_t h0, h1, h2, h3, u0, u1, u2, u3;
                    LDSM4(h0, h1, h2, h3, kvb + off);
                    LDSM4(u0, u1, u2, u3, kvb + 16384 + off);
                    uint32_t bh0[2] = {h0, h1}, bh1[2] = {h2, h3};
                    uint32_t bl0[2] = {u0, u1}, bl1[2] = {u2, u3};
                    MMA16816(sacc[2 * p],     qh, bh0);
                    MMA16816(sacc[2 * p],     qh, bl0);
                    MMA16816(sacc[2 * p],     ql, bh0);
                    MMA16816(sacc[2 * p + 1], qh, bh1);
                    MMA16816(sacc[2 * p + 1], qh, bl1);
                    MMA16816(sacc[2 * p + 1], ql, bh1);
                }
            }

            // ---- exp2-domain scale + causal mask ----
#pragma unroll
            for (int nt = 0; nt < 4; nt++)
#pragma unroll
                for (int j = 0; j < 4; j++) sacc[nt][j] *= SCALE2;
            if (kt == qt) {
#pragma unroll
                for (int nt = 0; nt < 4; nt++) {
                    const int c0 = wh * 32 + nt * 8 + tig * 2, c1 = c0 + 1;
                    if (c0 > r0) sacc[nt][0] = MASKV;
                    if (c1 > r0) sacc[nt][1] = MASKV;
                    if (c0 > r1) sacc[nt][2] = MASKV;
                    if (c1 > r1) sacc[nt][3] = MASKV;
                }
            }

            // ---- local max over this half's 32 cols ----
            float rm0 = MASKV, rm1 = MASKV;
#pragma unroll
            for (int nt = 0; nt < 4; nt++) {
                rm0 = fmaxf(rm0, fmaxf(sacc[nt][0], sacc[nt][1]));
                rm1 = fmaxf(rm1, fmaxf(sacc[nt][2], sacc[nt][3]));
            }
            rm0 = fmaxf(rm0, __shfl_xor_sync(0xffffffffu, rm0, 1));
            rm0 = fmaxf(rm0, __shfl_xor_sync(0xffffffffu, rm0, 2));
            rm1 = fmaxf(rm1, __shfl_xor_sync(0xffffffffu, rm1, 1));
            rm1 = fmaxf(rm1, __shfl_xor_sync(0xffffffffu, rm1, 2));
            if (tig == 0) {
                mPart[wh * 64 + r0] = rm0;
                mPart[wh * 64 + r1] = rm1;
            }

            // ---- exponentiate vs local max immediately ----
            float rs0 = 0.f, rs1 = 0.f;
#pragma unroll
            for (int nt = 0; nt < 4; nt++) {
                float p0 = exp2f(sacc[nt][0] - rm0);
                float p1 = exp2f(sacc[nt][1] - rm0);
                float p2 = exp2f(sacc[nt][2] - rm1);
                float p3 = exp2f(sacc[nt][3] - rm1);
                sacc[nt][0] = p0; sacc[nt][1] = p1;
                sacc[nt][2] = p2; sacc[nt][3] = p3;
                rs0 += p0 + p1; rs1 += p2 + p3;
            }
            rs0 += __shfl_xor_sync(0xffffffffu, rs0, 1);
            rs0 += __shfl_xor_sync(0xffffffffu, rs0, 2);
            rs1 += __shfl_xor_sync(0xffffffffu, rs1, 1);
            rs1 += __shfl_xor_sync(0xffffffffu, rs1, 2);
            if (tig == 0) {
                sPart[wh * 64 + r0] = rs0;
                sPart[wh * 64 + r1] = rs1;
            }
            __syncthreads();

            const float rmA0 = mPart[r0], rmB0 = mPart[64 + r0];
            const float rmA1 = mPart[r1], rmB1 = mPart[64 + r1];
            const float mn0 = fmaxf(m0, fmaxf(rmA0, rmB0));
            const float mn1 = fmaxf(m1, fmaxf(rmA1, rmB1));
            const float corr0 = exp2f(m0 - mn0), corr1 = exp2f(m1 - mn1);
            l0 = l0 * corr0 + sPart[r0]      * exp2f(rmA0 - mn0)
                            + sPart[64 + r0] * exp2f(rmB0 - mn0);
            l1 = l1 * corr1 + sPart[r1]      * exp2f(rmA1 - mn1)
                            + sPart[64 + r1] * exp2f(rmB1 - mn1);
            m0 = mn0; m1 = mn1;
            const float fac0 = exp2f(rm0 - mn0);
            const float fac1 = exp2f(rm1 - mn1);

#pragma unroll
            for (int t = 0; t < 16; t++) {
                oacc[t][0] *= corr0; oacc[t][1] *= corr0;
                oacc[t][2] *= corr1; oacc[t][3] *= corr1;
            }

            // ---- P fragments in-register (rescale folded into pack) ----
            uint32_t ph[2][4], pl[2][4];
#pragma unroll
            for (int c = 0; c < 2; c++) {
#pragma unroll
                for (int half = 0; half < 2; half++) {
                    const int nt = 2 * c + half;
                    float a0 = sacc[nt][0] * fac0, a1 = sacc[nt][1] * fac0;
                    float a2 = sacc[nt][2] * fac1, a3 = sacc[nt][3] * fac1;
                    __nv_bfloat16 h0 = __float2bfloat16(a0);
                    __nv_bfloat16 h1 = __float2bfloat16(a1);
                    __nv_bfloat16 h2 = __float2bfloat16(a2);
                    __nv_bfloat16 h3 = __float2bfloat16(a3);
                    ph[c][2 * half] =
                        (uint32_t)__bfloat16_as_ushort(h0) |
                        ((uint32_t)__bfloat16_as_ushort(h1) << 16);
                    ph[c][2 * half + 1] =
                        (uint32_t)__bfloat16_as_ushort(h2) |
                        ((uint32_t)__bfloat16_as_ushort(h3) << 16);
                    pl[c][2 * half] =
                        pack_bf(a0 - __bfloat162float(h0), a1 - __bfloat162float(h1));
                    pl[c][2 * half + 1] =
                        pack_bf(a2 - __bfloat162float(h2), a3 - __bfloat162float(h3));
                }
            }

            // ---- O += P V over this warp's 32 P-cols (3-term) ----
#pragma unroll
            for (int c = 0; c < 2; c++) {
                const uint32_t roff = (uint32_t)(((wh * 2 + c) * 16 + rk) * 256);
#pragma unroll
                for (int jp = 0; jp < 8; jp++) {
                    const int gq = jp * 2 + b3;
                    const uint32_t off = roff + (uint32_t)((gq ^ xr7) << 4);
                    uint32_t t0, t1, t2, t3, u0, u1, u2, u3;
                    LDSM4T(t0, t1, t2, t3, kvb + 32768 + off);
                    LDSM4T(u0, u1, u2, u3, kvb + 49152 + off);
                    uint32_t vh0[2] = {t0, t2}, vh1[2] = {t1, t3};
                    uint32_t vl0[2] = {u0, u2}, vl1[2] = {u1, u3};
                    MMA16816(oacc[2 * jp],     ph[c], vh0);
                    MMA16816(oacc[2 * jp],     ph[c], vl0);
                    MMA16816(oacc[2 * jp],     pl[c], vh0);
                    MMA16816(oacc[2 * jp + 1], ph[c], vh1);
                    MMA16816(oacc[2 * jp + 1], ph[c], vl1);
                    MMA16816(oacc[2 * jp + 1], pl[c], vh1);
                }
            }
            __syncthreads();
        }

        // ---- merge partial O between col-half partners, then store ----
        __syncthreads();
        if (wh == 1) {
            float* buf = (float*)(smA + AKV0 + wr * 8192);
#pragma unroll
            for (int t = 0; t < 16; t++) {
                const int col = t * 8 + tig * 2;
                *(float2*)&buf[g4 * 128 + col] =
                    make_float2(oacc[t][0], oacc[t][1]);
                *(float2*)&buf[(g4 + 8) * 128 + col] =
                    make_float2(oacc[t][2], oacc[t][3]);
            }
        }
        __syncthreads();
        if (wh == 0) {
            const float* buf = (const float*)(smA + AKV0 + wr * 8192);
            const float inv0 = 1.f / l0, inv1 = 1.f / l1;
#pragma unroll
            for (int t = 0; t < 16; t++) {
                const int col = t * 8 + tig * 2;
                float2 p0 = *(const float2*)&buf[g4 * 128 + col];
                float2 p1 = *(const float2*)&buf[(g4 + 8) * 128 + col];
                *(float2*)(out + qbase + (size_t)r0 * H_ + col) =
                    make_float2((oacc[t][0] + p0.x) * inv0,
                                (oacc[t][1] + p0.y) * inv0);
                *(float2*)(out + qbase + (size_t)r1 * H_ + col) =
                    make_float2((oacc[t][2] + p1.x) * inv1,
                                (oacc[t][3] + p1.y) * inv1);
            }
        }
    }
}

// ---------------------------------------------------------------------------
extern "C" void kernel_launch(void* const* d_in, const int* in_sizes, int n_in,
                              void* d_out, int out_size)
{
    const float* x  = (const float*)d_in[0];
    const float* Wq = (const float*)d_in[1];
    const float* Wk = (const float*)d_in[2];
    const float* Wv = (const float*)d_in[3];
    float* out = (float*)d_out;

    prep_kernel<<<16768, 256>>>(x, Wq, Wk, Wv);

    cudaFuncSetAttribute(qkv_mma_kernel,
                         cudaFuncAttributeMaxDynamicSharedMemorySize, QK_SMEM);
    qkv_mma_kernel<<<dim3(128, 3), 256, QK_SMEM>>>();

    cudaFuncSetAttribute(attn_mma_kernel,
                         cudaFuncAttributeMaxDynamicSharedMemorySize, ATT_SMEM);
    attn_mma_kernel<<<dim3(16, 8), 256, ATT_SMEM>>>(out);
}

// round 11
// speedup vs baseline: 1.0836x; 1.0359x over previous
#include <cuda_runtime.h>
#include <cuda_bf16.h>
#include <math.h>
#include <stdint.h>

#define B_ 8
#define T_ 2048
#define D_ 1024
#define H_ 128
#define SCALE2 0.12751763226289247f   // log2(e)/sqrt(128)
#define MASKV  (-1e30f)

__device__ __forceinline__ uint32_t smem_u32(const void* p) {
    uint32_t a;
    asm("{ .reg .u64 t; cvta.to.shared.u64 t, %1; cvt.u32.u64 %0, t; }"
        : "=r"(a) : "l"(p));
    return a;
}
__device__ __forceinline__ uint32_t pack_bf(float a, float b) {
    __nv_bfloat162 t = __floats2bfloat162_rn(a, b);
    return *reinterpret_cast<uint32_t*>(&t);
}

#define CP16(dst, src) \
    asm volatile("cp.async.cg.shared.global [%0], [%1], 16;" \
                 :: "r"(dst), "l"(src) : "memory")
#define CP_COMMIT() asm volatile("cp.async.commit_group;" ::: "memory")
#define CP_WAIT0()  asm volatile("cp.async.wait_group 0;" ::: "memory")
#define CP_WAIT1()  asm volatile("cp.async.wait_group 1;" ::: "memory")

#define LDSM4(r0, r1, r2, r3, addr) \
    asm volatile("ldmatrix.sync.aligned.m8n8.x4.shared.b16 {%0,%1,%2,%3}, [%4];" \
                 : "=r"(r0), "=r"(r1), "=r"(r2), "=r"(r3) : "r"(addr))
#define LDSM4T(r0, r1, r2, r3, addr) \
    asm volatile("ldmatrix.sync.aligned.m8n8.x4.trans.shared.b16 {%0,%1,%2,%3}, [%4];" \
                 : "=r"(r0), "=r"(r1), "=r"(r2), "=r"(r3) : "r"(addr))

#define MMA16816(d, a, b) \
    asm volatile("mma.sync.aligned.m16n8k16.row.col.f32.bf16.bf16.f32 " \
                 "{%0,%1,%2,%3},{%4,%5,%6,%7},{%8,%9},{%0,%1,%2,%3};" \
                 : "+f"((d)[0]), "+f"((d)[1]), "+f"((d)[2]), "+f"((d)[3]) \
                 : "r"((a)[0]), "r"((a)[1]), "r"((a)[2]), "r"((a)[3]), \
                   "r"((b)[0]), "r"((b)[1]))

// ---- device scratch ----
__device__ __nv_bfloat16 g_q_hi[(size_t)B_ * T_ * H_];
__device__ __nv_bfloat16 g_q_lo[(size_t)B_ * T_ * H_];
__device__ __nv_bfloat16 g_k_hi[(size_t)B_ * T_ * H_];
__device__ __nv_bfloat16 g_k_lo[(size_t)B_ * T_ * H_];
__device__ __nv_bfloat16 g_v_hi[(size_t)B_ * T_ * H_];
__device__ __nv_bfloat16 g_v_lo[(size_t)B_ * T_ * H_];
__device__ __nv_bfloat16 g_Wb_hi[384 * 1024];
__device__ __nv_bfloat16 g_Wb_lo[384 * 1024];
__device__ __nv_bfloat16 g_x_hi[(size_t)B_ * T_ * D_];
__device__ __nv_bfloat16 g_x_lo[(size_t)B_ * T_ * D_];

// ---------------------------------------------------------------------------
// Fused prep, MLP=4: blocks [0,4096) convert X (4 float4 per thread);
// blocks [4096,4480) convert Wcat.
// ---------------------------------------------------------------------------
__global__ __launch_bounds__(256) void prep_kernel(
    const float* __restrict__ x,
    const float* __restrict__ Wq,
    const float* __restrict__ Wk,
    const float* __restrict__ Wv)
{
    if (blockIdx.x < 4096) {
        const size_t base = (size_t)blockIdx.x * 1024 + threadIdx.x;
        float4 f[4];
#pragma unroll
        for (int k = 0; k < 4; k++) f[k] = ((const float4*)x)[base + k * 256];
#pragma unroll
        for (int k = 0; k < 4; k++) {
            __nv_bfloat16 h0 = __float2bfloat16(f[k].x);
            __nv_bfloat16 h1 = __float2bfloat16(f[k].y);
            __nv_bfloat16 h2 = __float2bfloat16(f[k].z);
            __nv_bfloat16 h3 = __float2bfloat16(f[k].w);
            uint2 hv, lv;
            hv.x = (uint32_t)__bfloat16_as_ushort(h0) |
                   ((uint32_t)__bfloat16_as_ushort(h1) << 16);
            hv.y = (uint32_t)__bfloat16_as_ushort(h2) |
                   ((uint32_t)__bfloat16_as_ushort(h3) << 16);
            lv.x = pack_bf(f[k].x - __bfloat162float(h0), f[k].y - __bfloat162float(h1));
            lv.y = pack_bf(f[k].z - __bfloat162float(h2), f[k].w - __bfloat162float(h3));
            ((uint2*)g_x_hi)[base + k * 256] = hv;
            ((uint2*)g_x_lo)[base + k * 256] = lv;
        }
    } else {
        const int n = blockIdx.x - 4096;
        const float* W = (n < 128) ? Wq : (n < 256 ? Wk : Wv);
        const int h = n & 127;
        for (int k = threadIdx.x; k < 1024; k += 256) {
            float w = W[(size_t)k * H_ + h];
            __nv_bfloat16 hi = __float2bfloat16(w);
            float lo = w - __bfloat162float(hi);
            g_Wb_hi[(size_t)n * 1024 + k] = hi;
            g_Wb_lo[(size_t)n * 1024 + k] = __float2bfloat16(lo);
        }
    }
}

// ---------------------------------------------------------------------------
// QKV GEMM: CTA tile 128x64, 256 thr, 8 warps 4x2, warp tile 32x32.
// K-chunk 64, 2-stage cp.async, 96KB smem -> 2 CTAs/SM.
// grid (6, 128): blockIdx.x = N-tile (fast) -> A-tile L2 reuse;
// blockIdx.y = M-tile.
// Stage layout: AH 0 | AL 16K | BH 32K | BL 40K  (48KB/stage).
// ---------------------------------------------------------------------------
#define QSTG 49152
#define QK_SMEM (2 * QSTG)

__device__ __forceinline__ void qkv_issue(uint32_t dstbase, int m0, int n0,
                                          int k0, int tid)
{
    // A: 1024 granules hi+lo
#pragma unroll
    for (int i = 0; i < 4; i++) {
        int idx = i * 256 + tid;
        int r = idx >> 3, g = idx & 7;
        uint32_t off = (uint32_t)(r * 128 + ((g ^ (r & 7)) << 4));
        const size_t ax = (size_t)(m0 + r) * D_ + k0 + g * 8;
        CP16(dstbase + off,         g_x_hi + ax);
        CP16(dstbase + 16384 + off, g_x_lo + ax);
    }
    // B: 512 granules hi+lo
#pragma unroll
    for (int i = 0; i < 2; i++) {
        int idx = i * 256 + tid;
        int r = idx >> 3, g = idx & 7;
        uint32_t off = (uint32_t)(r * 128 + ((g ^ (r & 7)) << 4));
        const size_t bx = (size_t)(n0 + r) * D_ + k0 + g * 8;
        CP16(dstbase + 32768 + off, g_Wb_hi + bx);
        CP16(dstbase + 40960 + off, g_Wb_lo + bx);
    }
}

__global__ __launch_bounds__(256, 2) void qkv_mma_kernel()
{
    extern __shared__ char smq[];
    const uint32_t sb = smem_u32(smq);
    const int tid  = threadIdx.x;
    const int lane = tid & 31, warp = tid >> 5;
    const int wm = warp >> 1, wn = warp & 1;
    const int m0 = blockIdx.y * 128;
    const int n0 = blockIdx.x * 64;      // global N (0..383)

    float acc[2][4][4];
#pragma unroll
    for (int mt = 0; mt < 2; mt++)
#pragma unroll
        for (int nt = 0; nt < 4; nt++)
#pragma unroll
            for (int j = 0; j < 4; j++) acc[mt][nt][j] = 0.f;

    uint32_t a_rb[2], a_xr[2];
#pragma unroll
    for (int mt = 0; mt < 2; mt++) {
        int rowA = wm * 32 + mt * 16 + (lane & 15);
        a_rb[mt] = (uint32_t)(rowA * 128);
        a_xr[mt] = (uint32_t)((rowA & 7) << 4);
    }
    const uint32_t a_cb = (uint32_t)((lane >> 4) * 16);
    uint32_t b_rb[2], b_xr[2];
#pragma unroll
    for (int p = 0; p < 2; p++) {
        int nB = wn * 32 + p * 16 + ((lane >> 4) << 3) + (lane & 7);
        b_rb[p] = (uint32_t)(nB * 128);
        b_xr[p] = (uint32_t)((nB & 7) << 4);
    }
    const uint32_t b_cb = (uint32_t)(((lane >> 3) & 1) * 16);

    qkv_issue(sb, m0, n0, 0, tid);
    CP_COMMIT();

    for (int kc = 0; kc < 16; kc++) {
        if (kc < 15) {
            qkv_issue(sb + (uint32_t)(((kc + 1) & 1) * QSTG),
                      m0, n0, (kc + 1) * 64, tid);
            CP_COMMIT();
            CP_WAIT1();
        } else {
            CP_WAIT0();
        }
        __syncthreads();

        const uint32_t bufb = sb + (uint32_t)((kc & 1) * QSTG);
#pragma unroll
        for (int ks = 0; ks < 4; ks++) {
            const uint32_t acol = (a_cb + ks * 32);
            const uint32_t bcol = (b_cb + ks * 32);
            uint32_t ah[2][4], al[2][4];
#pragma unroll
            for (int mt = 0; mt < 2; mt++) {
                LDSM4(ah[mt][0], ah[mt][1], ah[mt][2], ah[mt][3],
                      bufb + a_rb[mt] + (acol ^ a_xr[mt]));
                LDSM4(al[mt][0], al[mt][1], al[mt][2], al[mt][3],
                      bufb + 16384 + a_rb[mt] + (acol ^ a_xr[mt]));
            }
            uint32_t bh[4][2], bl[4][2];
#pragma unroll
            for (int p = 0; p < 2; p++) {
                uint32_t r0, r1, r2, r3;
                LDSM4(r0, r1, r2, r3, bufb + 32768 + b_rb[p] + (bcol ^ b_xr[p]));
                bh[2 * p][0] = r0; bh[2 * p][1] = r1;
                bh[2 * p + 1][0] = r2; bh[2 * p + 1][1] = r3;
                LDSM4(r0, r1, r2, r3, bufb + 40960 + b_rb[p] + (bcol ^ b_xr[p]));
                bl[2 * p][0] = r0; bl[2 * p][1] = r1;
                bl[2 * p + 1][0] = r2; bl[2 * p + 1][1] = r3;
            }
#pragma unroll
            for (int mt = 0; mt < 2; mt++)
#pragma unroll
                for (int nt = 0; nt < 4; nt++) {
                    MMA16816(acc[mt][nt], ah[mt], bh[nt]);
                    MMA16816(acc[mt][nt], ah[mt], bl[nt]);
                    MMA16816(acc[mt][nt], al[mt], bh[nt]);
                }
        }
        __syncthreads();
    }

    // ---- epilogue: n0 selects q/k/v and column half ----
    const int sel = n0 >> 7;                   // 0,1,2
    __nv_bfloat16* oh = (sel == 0) ? g_q_hi : (sel == 1 ? g_k_hi : g_v_hi);
    __nv_bfloat16* ol = (sel == 0) ? g_q_lo : (sel == 1 ? g_k_lo : g_v_lo);
    const int colbase = n0 & 127;              // 0 or 64
    const int g = lane >> 2, tig = lane & 3;
#pragma unroll
    for (int mt = 0; mt < 2; mt++) {
        const int row0 = m0 + wm * 32 + mt * 16 + g;
#pragma unroll
        for (int nt = 0; nt < 4; nt++) {
            const int col = colbase + wn * 32 + nt * 8 + tig * 2;
#pragma unroll
            for (int h = 0; h < 2; h++) {
                const int row = row0 + h * 8;
                float a0 = acc[mt][nt][2 * h], a1 = acc[mt][nt][2 * h + 1];
                __nv_bfloat16 h0 = __float2bfloat16(a0);
                __nv_bfloat16 h1 = __float2bfloat16(a1);
                *(uint32_t*)(oh + (size_t)row * H_ + col) =
                    (uint32_t)__bfloat16_as_ushort(h0) |
                    ((uint32_t)__bfloat16_as_ushort(h1) << 16);
                *(uint32_t*)(ol + (size_t)row * H_ + col) =
                    pack_bf(a0 - __bfloat162float(h0), a1 - __bfloat162float(h1));
            }
        }
    }
}

// ---------------------------------------------------------------------------
// Flash attention (R10, unchanged): 256 threads, 4 row-groups x 2 col-halves,
// exp2 single-barrier softmax, Q fragments reloaded from smem.
// ---------------------------------------------------------------------------
#define AQH 0
#define AQL 16384
#define AKV0 32768
#define KVBUF 65536
#define AEXM 163840
#define AEXS 164352
#define ATT_SMEM 164864

__device__ __forceinline__ void kv_issue256(uint32_t dstbase, size_t kbase, int tid)
{
#pragma unroll
    for (int i = 0; i < 4; i++) {
        int idx = i * 256 + tid;
        int r = idx >> 4, gq = idx & 15;
        uint32_t off = (uint32_t)(r * 256 + ((gq ^ (r & 7)) << 4));
        const size_t ge = kbase + (size_t)r * 128 + gq * 8;
        CP16(dstbase + off,         g_k_hi + ge);
        CP16(dstbase + 16384 + off, g_k_lo + ge);
        CP16(dstbase + 32768 + off, g_v_hi + ge);
        CP16(dstbase + 49152 + off, g_v_lo + ge);
    }
}

__global__ __launch_bounds__(256, 1) void attn_mma_kernel(float* __restrict__ out)
{
    extern __shared__ char smA[];
    const uint32_t sb = smem_u32(smA);
    float* mPart = (float*)(smA + AEXM);
    float* sPart = (float*)(smA + AEXS);

    const int tid  = threadIdx.x;
    const int lane = tid & 31, warp = tid >> 5;
    const int wr = warp & 3;
    const int wh = warp >> 2;
    const int b    = blockIdx.y;
    const int g4   = lane >> 2, tig = lane & 3;
    const int b3   = (lane >> 3) & 1;
    const int rk   = ((lane >> 4) << 3) + (lane & 7);
    const int xr7  = lane & 7;

    const int qrow = wr * 16 + (lane & 15);
    const uint32_t q_rb = (uint32_t)(qrow * 256);
    const uint32_t q_xr = (uint32_t)((qrow & 7));

    for (int pass = 0; pass < 2; pass++) {
        const int qt = pass ? (31 - (int)blockIdx.x) : (int)blockIdx.x;
        const size_t qbase = ((size_t)b * T_ + (size_t)qt * 64) * H_;
        const size_t batchbase = (size_t)b * T_ * H_;

        __syncthreads();
        kv_issue256(sb + AKV0, batchbase, tid);
        CP_COMMIT();

#pragma unroll
        for (int i = 0; i < 4; i++) {
            int idx = i * 256 + tid;
            int r = idx >> 4, gq = idx & 15;
            uint32_t off = (uint32_t)(r * 256 + ((gq ^ (r & 7)) << 4));
            *(uint4*)(smA + AQH + off) = *(const uint4*)(g_q_hi + qbase + r * 128 + gq * 8);
            *(uint4*)(smA + AQL + off) = *(const uint4*)(g_q_lo + qbase + r * 128 + gq * 8);
        }

        float oacc[16][4];
#pragma unroll
        for (int t = 0; t < 16; t++)
#pragma unroll
            for (int j = 0; j < 4; j++) oacc[t][j] = 0.f;
        float m0 = MASKV, m1 = MASKV, l0 = 0.f, l1 = 0.f;

        const int r0 = wr * 16 + g4, r1 = r0 + 8;

        for (int kt = 0; kt <= qt; kt++) {
            if (kt < qt) {
                kv_issue256(sb + AKV0 + (uint32_t)(((kt + 1) & 1) * KVBUF),
                            batchbase + (size_t)(kt + 1) * 64 * H_, tid);
                CP_COMMIT();
                CP_WAIT1();
            } else {
                CP_WAIT0();
            }
            __syncthreads();
            const uint32_t kvb = sb + AKV0 + (uint32_t)((kt & 1) * KVBUF);

            float sacc[4][4];
#pragma unroll
            for (int nt = 0; nt < 4; nt++)
#pragma unroll
                for (int j = 0; j < 4; j++) sacc[nt][j] = 0.f;

#pragma unroll
            for (int ks = 0; ks < 8; ks++) {
                uint32_t qh[4], ql[4];
                {
                    int gq = ks * 2 + (lane >> 4);
                    uint32_t off = q_rb + (uint32_t)((gq ^ q_xr) << 4);
                    LDSM4(qh[0], qh[1], qh[2], qh[3], sb + AQH + off);
                    LDSM4(ql[0], ql[1], ql[2], ql[3], sb + AQL + off);
                }
                const int gq = ks * 2 + b3;
                const uint32_t csw = (uint32_t)((gq ^ xr7) << 4);
#pragma unroll
                for (int p = 0; p < 2; p++) {
                    const uint32_t off =
                        (uint32_t)((wh * 32 + p * 16 + rk) * 256) + csw;
                    uint32_t h0, h1, h2, h3, u0, u1, u2, u3;
                    LDSM4(h0, h1, h2, h3, kvb + off);
                    LDSM4(u0, u1, u2, u3, kvb + 16384 + off);
                    uint32_t bh0[2] = {h0, h1}, bh1[2] = {h2, h3};
                    uint32_t bl0[2] = {u0, u1}, bl1[2] = {u2, u3};
                    MMA16816(sacc[2 * p],     qh, bh0);
                    MMA16816(sacc[2 * p],     qh, bl0);
                    MMA16816(sacc[2 * p],     ql, bh0);
                    MMA16816(sacc[2 * p + 1], qh, bh1);
                    MMA16816(sacc[2 * p + 1], qh, bl1);
                    MMA16816(sacc[2 * p + 1], ql, bh1);
                }
            }

#pragma unroll
            for (int nt = 0; nt < 4; nt++)
#pragma unroll
                for (int j = 0; j < 4; j++) sacc[nt][j] *= SCALE2;
            if (kt == qt) {
#pragma unroll
                for (int nt = 0; nt < 4; nt++) {
                    const int c0 = wh * 32 + nt * 8 + tig * 2, c1 = c0 + 1;
                    if (c0 > r0) sacc[nt][0] = MASKV;
                    if (c1 > r0) sacc[nt][1] = MASKV;
                    if (c0 > r1) sacc[nt][2] = MASKV;
                    if (c1 > r1) sacc[nt][3] = MASKV;
                }
            }

            float rm0 = MASKV, rm1 = MASKV;
#pragma unroll
            for (int nt = 0; nt < 4; nt++) {
                rm0 = fmaxf(rm0, fmaxf(sacc[nt][0], sacc[nt][1]));
                rm1 = fmaxf(rm1, fmaxf(sacc[nt][2], sacc[nt][3]));
            }
            rm0 = fmaxf(rm0, __shfl_xor_sync(0xffffffffu, rm0, 1));
            rm0 = fmaxf(rm0, __shfl_xor_sync(0xffffffffu, rm0, 2));
            rm1 = fmaxf(rm1, __shfl_xor_sync(0xffffffffu, rm1, 1));
            rm1 = fmaxf(rm1, __shfl_xor_sync(0xffffffffu, rm1, 2));
            if (tig == 0) {
                mPart[wh * 64 + r0] = rm0;
                mPart[wh * 64 + r1] = rm1;
            }

            float rs0 = 0.f, rs1 = 0.f;
#pragma unroll
            for (int nt = 0; nt < 4; nt++) {
                float p0 = exp2f(sacc[nt][0] - rm0);
                float p1 = exp2f(sacc[nt][1] - rm0);
                float p2 = exp2f(sacc[nt][2] - rm1);
                float p3 = exp2f(sacc[nt][3] - rm1);
                sacc[nt][0] = p0; sacc[nt][1] = p1;
                sacc[nt][2] = p2; sacc[nt][3] = p3;
                rs0 += p0 + p1; rs1 += p2 + p3;
            }
            rs0 += __shfl_xor_sync(0xffffffffu, rs0, 1);
            rs0 += __shfl_xor_sync(0xffffffffu, rs0, 2);
            rs1 += __shfl_xor_sync(0xffffffffu, rs1, 1);
            rs1 += __shfl_xor_sync(0xffffffffu, rs1, 2);
            if (tig == 0) {
                sPart[wh * 64 + r0] = rs0;
                sPart[wh * 64 + r1] = rs1;
            }
            __syncthreads();

            const float rmA0 = mPart[r0], rmB0 = mPart[64 + r0];
            const float rmA1 = mPart[r1], rmB1 = mPart[64 + r1];
            const float mn0 = fmaxf(m0, fmaxf(rmA0, rmB0));
            const float mn1 = fmaxf(m1, fmaxf(rmA1, rmB1));
            const float corr0 = exp2f(m0 - mn0), corr1 = exp2f(m1 - mn1);
            l0 = l0 * corr0 + sPart[r0]      * exp2f(rmA0 - mn0)
                            + sPart[64 + r0] * exp2f(rmB0 - mn0);
            l1 = l1 * corr1 + sPart[r1]      * exp2f(rmA1 - mn1)
                            + sPart[64 + r1] * exp2f(rmB1 - mn1);
            m0 = mn0; m1 = mn1;
            const float fac0 = exp2f(rm0 - mn0);
            const float fac1 = exp2f(rm1 - mn1);

#pragma unroll
            for (int t = 0; t < 16; t++) {
                oacc[t][0] *= corr0; oacc[t][1] *= corr0;
                oacc[t][2] *= corr1; oacc[t][3] *= corr1;
            }

            uint32_t ph[2][4], pl[2][4];
#pragma unroll
            for (int c = 0; c < 2; c++) {
#pragma unroll
                for (int half = 0; half < 2; half++) {
                    const int nt = 2 * c + half;
                    float a0 = sacc[nt][0] * fac0, a1 = sacc[nt][1] * fac0;
                    float a2 = sacc[nt][2] * fac1, a3 = sacc[nt][3] * fac1;
                    __nv_bfloat16 h0 = __float2bfloat16(a0);
                    __nv_bfloat16 h1 = __float2bfloat16(a1);
                    __nv_bfloat16 h2 = __float2bfloat16(a2);
                    __nv_bfloat16 h3 = __float2bfloat16(a3);
                    ph[c][2 * half] =
                        (uint32_t)__bfloat16_as_ushort(h0) |
                        ((uint32_t)__bfloat16_as_ushort(h1) << 16);
                    ph[c][2 * half + 1] =
                        (uint32_t)__bfloat16_as_ushort(h2) |
                        ((uint32_t)__bfloat16_as_ushort(h3) << 16);
                    pl[c][2 * half] =
                        pack_bf(a0 - __bfloat162float(h0), a1 - __bfloat162float(h1));
                    pl[c][2 * half + 1] =
                        pack_bf(a2 - __bfloat162float(h2), a3 - __bfloat162float(h3));
                }
            }

#pragma unroll
            for (int c = 0; c < 2; c++) {
                const uint32_t roff = (uint32_t)(((wh * 2 + c) * 16 + rk) * 256);
#pragma unroll
                for (int jp = 0; jp < 8; jp++) {
                    const int gq = jp * 2 + b3;
                    const uint32_t off = roff + (uint32_t)((gq ^ xr7) << 4);
                    uint32_t t0, t1, t2, t3, u0, u1, u2, u3;
                    LDSM4T(t0, t1, t2, t3, kvb + 32768 + off);
                    LDSM4T(u0, u1, u2, u3, kvb + 49152 + off);
                    uint32_t vh0[2] = {t0, t2}, vh1[2] = {t1, t3};
                    uint32_t vl0[2] = {u0, u2}, vl1[2] = {u1, u3};
                    MMA16816(oacc[2 * jp],     ph[c], vh0);
                    MMA16816(oacc[2 * jp],     ph[c], vl0);
                    MMA16816(oacc[2 * jp],     pl[c], vh0);
                    MMA16816(oacc[2 * jp + 1], ph[c], vh1);
                    MMA16816(oacc[2 * jp + 1], ph[c], vl1);
                    MMA16816(oacc[2 * jp + 1], pl[c], vh1);
                }
            }
            __syncthreads();
        }

        __syncthreads();
        if (wh == 1) {
            float* buf = (float*)(smA + AKV0 + wr * 8192);
#pragma unroll
            for (int t = 0; t < 16; t++) {
                const int col = t * 8 + tig * 2;
                *(float2*)&buf[g4 * 128 + col] =
                    make_float2(oacc[t][0], oacc[t][1]);
                *(float2*)&buf[(g4 + 8) * 128 + col] =
                    make_float2(oacc[t][2], oacc[t][3]);
            }
        }
        __syncthreads();
        if (wh == 0) {
            const float* buf = (const float*)(smA + AKV0 + wr * 8192);
            const float inv0 = 1.f / l0, inv1 = 1.f / l1;
#pragma unroll
            for (int t = 0; t < 16; t++) {
                const int col = t * 8 + tig * 2;
                float2 p0 = *(const float2*)&buf[g4 * 128 + col];
                float2 p1 = *(const float2*)&buf[(g4 + 8) * 128 + col];
                *(float2*)(out + qbase + (size_t)r0 * H_ + col) =
                    make_float2((oacc[t][0] + p0.x) * inv0,
                                (oacc[t][1] + p0.y) * inv0);
                *(float2*)(out + qbase + (size_t)r1 * H_ + col) =
                    make_float2((oacc[t][2] + p1.x) * inv1,
                                (oacc[t][3] + p1.y) * inv1);
            }
        }
    }
}

// ---------------------------------------------------------------------------
extern "C" void kernel_launch(void* const* d_in, const int* in_sizes, int n_in,
                              void* d_out, int out_size)
{
    const float* x  = (const float*)d_in[0];
    const float* Wq = (const float*)d_in[1];
    const float* Wk = (const float*)d_in[2];
    const float* Wv = (const float*)d_in[3];
    float* out = (float*)d_out;

    prep_kernel<<<4480, 256>>>(x, Wq, Wk, Wv);

    cudaFuncSetAttribute(qkv_mma_kernel,
                         cudaFuncAttributeMaxDynamicSharedMemorySize, QK_SMEM);
    qkv_mma_kernel<<<dim3(6, 128), 256, QK_SMEM>>>();

    cudaFuncSetAttribute(attn_mma_kernel,
                         cudaFuncAttributeMaxDynamicSharedMemorySize, ATT_SMEM);
    attn_mma_kernel<<<dim3(16, 8), 256, ATT_SMEM>>>(out);
}

// round 12
// speedup vs baseline: 1.2420x; 1.1462x over previous
#include <cuda_runtime.h>
#include <cuda_bf16.h>
#include <cuda_fp16.h>
#include <math.h>
#include <stdint.h>

#define B_ 8
#define T_ 2048
#define D_ 1024
#define H_ 128
#define SCALE2 0.12751763226289247f   // log2(e)/sqrt(128)
#define MASKV  (-1e30f)

__device__ __forceinline__ uint32_t smem_u32(const void* p) {
    uint32_t a;
    asm("{ .reg .u64 t; cvta.to.shared.u64 t, %1; cvt.u32.u64 %0, t; }"
        : "=r"(a) : "l"(p));
    return a;
}
__device__ __forceinline__ uint32_t pack_bf(float a, float b) {
    __nv_bfloat162 t = __floats2bfloat162_rn(a, b);
    return *reinterpret_cast<uint32_t*>(&t);
}
__device__ __forceinline__ uint32_t pack_h2(float a, float b) {
    __half2 t = __floats2half2_rn(a, b);
    return *reinterpret_cast<uint32_t*>(&t);
}

#define CP16(dst, src) \
    asm volatile("cp.async.cg.shared.global [%0], [%1], 16;" \
                 :: "r"(dst), "l"(src) : "memory")
#define CP_COMMIT() asm volatile("cp.async.commit_group;" ::: "memory")
#define CP_WAIT0()  asm volatile("cp.async.wait_group 0;" ::: "memory")
#define CP_WAIT1()  asm volatile("cp.async.wait_group 1;" ::: "memory")

#define LDSM4(r0, r1, r2, r3, addr) \
    asm volatile("ldmatrix.sync.aligned.m8n8.x4.shared.b16 {%0,%1,%2,%3}, [%4];" \
                 : "=r"(r0), "=r"(r1), "=r"(r2), "=r"(r3) : "r"(addr))
#define LDSM4T(r0, r1, r2, r3, addr) \
    asm volatile("ldmatrix.sync.aligned.m8n8.x4.trans.shared.b16 {%0,%1,%2,%3}, [%4];" \
                 : "=r"(r0), "=r"(r1), "=r"(r2), "=r"(r3) : "r"(addr))

#define MMA16816(d, a, b) \
    asm volatile("mma.sync.aligned.m16n8k16.row.col.f32.bf16.bf16.f32 " \
                 "{%0,%1,%2,%3},{%4,%5,%6,%7},{%8,%9},{%0,%1,%2,%3};" \
                 : "+f"((d)[0]), "+f"((d)[1]), "+f"((d)[2]), "+f"((d)[3]) \
                 : "r"((a)[0]), "r"((a)[1]), "r"((a)[2]), "r"((a)[3]), \
                   "r"((b)[0]), "r"((b)[1]))

#define MMA16816H(d, a, b) \
    asm volatile("mma.sync.aligned.m16n8k16.row.col.f32.f16.f16.f32 " \
                 "{%0,%1,%2,%3},{%4,%5,%6,%7},{%8,%9},{%0,%1,%2,%3};" \
                 : "+f"((d)[0]), "+f"((d)[1]), "+f"((d)[2]), "+f"((d)[3]) \
                 : "r"((a)[0]), "r"((a)[1]), "r"((a)[2]), "r"((a)[3]), \
                   "r"((b)[0]), "r"((b)[1]))

// ---- device scratch ----
__device__ __half g_q_hi[(size_t)B_ * T_ * H_];
__device__ __half g_q_lo[(size_t)B_ * T_ * H_];
__device__ __half g_k_hi[(size_t)B_ * T_ * H_];
__device__ __half g_v_hi[(size_t)B_ * T_ * H_];
__device__ __nv_bfloat16 g_Wb_hi[384 * 1024];
__device__ __nv_bfloat16 g_Wb_lo[384 * 1024];
__device__ __nv_bfloat16 g_x_hi[(size_t)B_ * T_ * D_];
__device__ __nv_bfloat16 g_x_lo[(size_t)B_ * T_ * D_];

// ---------------------------------------------------------------------------
// Fused prep, MLP=4
// ---------------------------------------------------------------------------
__global__ __launch_bounds__(256) void prep_kernel(
    const float* __restrict__ x,
    const float* __restrict__ Wq,
    const float* __restrict__ Wk,
    const float* __restrict__ Wv)
{
    if (blockIdx.x < 4096) {
        const size_t base = (size_t)blockIdx.x * 1024 + threadIdx.x;
        float4 f[4];
#pragma unroll
        for (int k = 0; k < 4; k++) f[k] = ((const float4*)x)[base + k * 256];
#pragma unroll
        for (int k = 0; k < 4; k++) {
            __nv_bfloat16 h0 = __float2bfloat16(f[k].x);
            __nv_bfloat16 h1 = __float2bfloat16(f[k].y);
            __nv_bfloat16 h2 = __float2bfloat16(f[k].z);
            __nv_bfloat16 h3 = __float2bfloat16(f[k].w);
            uint2 hv, lv;
            hv.x = (uint32_t)__bfloat16_as_ushort(h0) |
                   ((uint32_t)__bfloat16_as_ushort(h1) << 16);
            hv.y = (uint32_t)__bfloat16_as_ushort(h2) |
                   ((uint32_t)__bfloat16_as_ushort(h3) << 16);
            lv.x = pack_bf(f[k].x - __bfloat162float(h0), f[k].y - __bfloat162float(h1));
            lv.y = pack_bf(f[k].z - __bfloat162float(h2), f[k].w - __bfloat162float(h3));
            ((uint2*)g_x_hi)[base + k * 256] = hv;
            ((uint2*)g_x_lo)[base + k * 256] = lv;
        }
    } else {
        const int n = blockIdx.x - 4096;
        const float* W = (n < 128) ? Wq : (n < 256 ? Wk : Wv);
        const int h = n & 127;
        for (int k = threadIdx.x; k < 1024; k += 256) {
            float w = W[(size_t)k * H_ + h];
            __nv_bfloat16 hi = __float2bfloat16(w);
            float lo = w - __bfloat162float(hi);
            g_Wb_hi[(size_t)n * 1024 + k] = hi;
            g_Wb_lo[(size_t)n * 1024 + k] = __float2bfloat16(lo);
        }
    }
}

// ---------------------------------------------------------------------------
// QKV GEMM: CTA 128x64, 256 thr, warps 4x2, 2 CTAs/SM. bf16 3-term (R11).
// Epilogue writes fp16: Q hi+lo, K/V hi only.
// ---------------------------------------------------------------------------
#define QSTG 49152
#define QK_SMEM (2 * QSTG)

__device__ __forceinline__ void qkv_issue(uint32_t dstbase, int m0, int n0,
                                          int k0, int tid)
{
#pragma unroll
    for (int i = 0; i < 4; i++) {
        int idx = i * 256 + tid;
        int r = idx >> 3, g = idx & 7;
        uint32_t off = (uint32_t)(r * 128 + ((g ^ (r & 7)) << 4));
        const size_t ax = (size_t)(m0 + r) * D_ + k0 + g * 8;
        CP16(dstbase + off,         g_x_hi + ax);
        CP16(dstbase + 16384 + off, g_x_lo + ax);
    }
#pragma unroll
    for (int i = 0; i < 2; i++) {
        int idx = i * 256 + tid;
        int r = idx >> 3, g = idx & 7;
        uint32_t off = (uint32_t)(r * 128 + ((g ^ (r & 7)) << 4));
        const size_t bx = (size_t)(n0 + r) * D_ + k0 + g * 8;
        CP16(dstbase + 32768 + off, g_Wb_hi + bx);
        CP16(dstbase + 40960 + off, g_Wb_lo + bx);
    }
}

__global__ __launch_bounds__(256, 2) void qkv_mma_kernel()
{
    extern __shared__ char smq[];
    const uint32_t sb = smem_u32(smq);
    const int tid  = threadIdx.x;
    const int lane = tid & 31, warp = tid >> 5;
    const int wm = warp >> 1, wn = warp & 1;
    const int m0 = blockIdx.y * 128;
    const int n0 = blockIdx.x * 64;

    float acc[2][4][4];
#pragma unroll
    for (int mt = 0; mt < 2; mt++)
#pragma unroll
        for (int nt = 0; nt < 4; nt++)
#pragma unroll
            for (int j = 0; j < 4; j++) acc[mt][nt][j] = 0.f;

    uint32_t a_rb[2], a_xr[2];
#pragma unroll
    for (int mt = 0; mt < 2; mt++) {
        int rowA = wm * 32 + mt * 16 + (lane & 15);
        a_rb[mt] = (uint32_t)(rowA * 128);
        a_xr[mt] = (uint32_t)((rowA & 7) << 4);
    }
    const uint32_t a_cb = (uint32_t)((lane >> 4) * 16);
    uint32_t b_rb[2], b_xr[2];
#pragma unroll
    for (int p = 0; p < 2; p++) {
        int nB = wn * 32 + p * 16 + ((lane >> 4) << 3) + (lane & 7);
        b_rb[p] = (uint32_t)(nB * 128);
        b_xr[p] = (uint32_t)((nB & 7) << 4);
    }
    const uint32_t b_cb = (uint32_t)(((lane >> 3) & 1) * 16);

    qkv_issue(sb, m0, n0, 0, tid);
    CP_COMMIT();

    for (int kc = 0; kc < 16; kc++) {
        if (kc < 15) {
            qkv_issue(sb + (uint32_t)(((kc + 1) & 1) * QSTG),
                      m0, n0, (kc + 1) * 64, tid);
            CP_COMMIT();
            CP_WAIT1();
        } else {
            CP_WAIT0();
        }
        __syncthreads();

        const uint32_t bufb = sb + (uint32_t)((kc & 1) * QSTG);
#pragma unroll
        for (int ks = 0; ks < 4; ks++) {
            const uint32_t acol = (a_cb + ks * 32);
            const uint32_t bcol = (b_cb + ks * 32);
            uint32_t ah[2][4], al[2][4];
#pragma unroll
            for (int mt = 0; mt < 2; mt++) {
                LDSM4(ah[mt][0], ah[mt][1], ah[mt][2], ah[mt][3],
                      bufb + a_rb[mt] + (acol ^ a_xr[mt]));
                LDSM4(al[mt][0], al[mt][1], al[mt][2], al[mt][3],
                      bufb + 16384 + a_rb[mt] + (acol ^ a_xr[mt]));
            }
            uint32_t bh[4][2], bl[4][2];
#pragma unroll
            for (int p = 0; p < 2; p++) {
                uint32_t r0, r1, r2, r3;
                LDSM4(r0, r1, r2, r3, bufb + 32768 + b_rb[p] + (bcol ^ b_xr[p]));
                bh[2 * p][0] = r0; bh[2 * p][1] = r1;
                bh[2 * p + 1][0] = r2; bh[2 * p + 1][1] = r3;
                LDSM4(r0, r1, r2, r3, bufb + 40960 + b_rb[p] + (bcol ^ b_xr[p]));
                bl[2 * p][0] = r0; bl[2 * p][1] = r1;
                bl[2 * p + 1][0] = r2; bl[2 * p + 1][1] = r3;
            }
#pragma unroll
            for (int mt = 0; mt < 2; mt++)
#pragma unroll
                for (int nt = 0; nt < 4; nt++) {
                    MMA16816(acc[mt][nt], ah[mt], bh[nt]);
                    MMA16816(acc[mt][nt], ah[mt], bl[nt]);
                    MMA16816(acc[mt][nt], al[mt], bh[nt]);
                }
        }
        __syncthreads();
    }

    // ---- epilogue: fp16 outputs. Q: hi+lo, K/V: hi only. ----
    const int sel = n0 >> 7;
    __half* oh = (sel == 0) ? g_q_hi : (sel == 1 ? g_k_hi : g_v_hi);
    const int colbase = n0 & 127;
    const int g = lane >> 2, tig = lane & 3;
#pragma unroll
    for (int mt = 0; mt < 2; mt++) {
        const int row0 = m0 + wm * 32 + mt * 16 + g;
#pragma unroll
        for (int nt = 0; nt < 4; nt++) {
            const int col = colbase + wn * 32 + nt * 8 + tig * 2;
#pragma unroll
            for (int h = 0; h < 2; h++) {
                const int row = row0 + h * 8;
                float a0 = acc[mt][nt][2 * h], a1 = acc[mt][nt][2 * h + 1];
                __half h0 = __float2half_rn(a0);
                __half h1 = __float2half_rn(a1);
                uint32_t hv = (uint32_t)__half_as_ushort(h0) |
                              ((uint32_t)__half_as_ushort(h1) << 16);
                *(uint32_t*)(oh + (size_t)row * H_ + col) = hv;
                if (sel == 0) {
                    *(uint32_t*)(g_q_lo + (size_t)row * H_ + col) =
                        pack_h2(a0 - __half2float(h0), a1 - __half2float(h1));
                }
            }
        }
    }
}

// ---------------------------------------------------------------------------
// Flash attention: fp16 2-term (Q hi/lo x K hi; P hi/lo x V hi).
// 256 threads, 4 row-groups x 2 col-halves. KV stage = 32KB (KH|VH).
// 2 barriers/tile: top(wait) + stat exchange; next-KV issued post-exchange.
// ---------------------------------------------------------------------------
#define AQH 0
#define AQL 16384
#define AKV0 32768
#define KVBUF 32768
#define AEXM 98304
#define AEXS 98816
#define ATT_SMEM 99328

__device__ __forceinline__ void kv_issue256(uint32_t dstbase, size_t kbase, int tid)
{
#pragma unroll
    for (int i = 0; i < 4; i++) {
        int idx = i * 256 + tid;
        int r = idx >> 4, gq = idx & 15;
        uint32_t off = (uint32_t)(r * 256 + ((gq ^ (r & 7)) << 4));
        const size_t ge = kbase + (size_t)r * 128 + gq * 8;
        CP16(dstbase + off,         g_k_hi + ge);
        CP16(dstbase + 16384 + off, g_v_hi + ge);
    }
}

__global__ __launch_bounds__(256, 1) void attn_mma_kernel(float* __restrict__ out)
{
    extern __shared__ char smA[];
    const uint32_t sb = smem_u32(smA);
    float* mPart = (float*)(smA + AEXM);
    float* sPart = (float*)(smA + AEXS);

    const int tid  = threadIdx.x;
    const int lane = tid & 31, warp = tid >> 5;
    const int wr = warp & 3;
    const int wh = warp >> 2;
    const int b    = blockIdx.y;
    const int g4   = lane >> 2, tig = lane & 3;
    const int b3   = (lane >> 3) & 1;
    const int rk   = ((lane >> 4) << 3) + (lane & 7);
    const int xr7  = lane & 7;

    const int qrow = wr * 16 + (lane & 15);
    const uint32_t q_rb = (uint32_t)(qrow * 256);
    const uint32_t q_xr = (uint32_t)((qrow & 7));

    for (int pass = 0; pass < 2; pass++) {
        const int qt = pass ? (31 - (int)blockIdx.x) : (int)blockIdx.x;
        const size_t qbase = ((size_t)b * T_ + (size_t)qt * 64) * H_;
        const size_t batchbase = (size_t)b * T_ * H_;

        __syncthreads();
        kv_issue256(sb + AKV0, batchbase, tid);
        CP_COMMIT();

#pragma unroll
        for (int i = 0; i < 4; i++) {
            int idx = i * 256 + tid;
            int r = idx >> 4, gq = idx & 15;
            uint32_t off = (uint32_t)(r * 256 + ((gq ^ (r & 7)) << 4));
            *(uint4*)(smA + AQH + off) = *(const uint4*)(g_q_hi + qbase + r * 128 + gq * 8);
            *(uint4*)(smA + AQL + off) = *(const uint4*)(g_q_lo + qbase + r * 128 + gq * 8);
        }

        float oacc[16][4];
#pragma unroll
        for (int t = 0; t < 16; t++)
#pragma unroll
            for (int j = 0; j < 4; j++) oacc[t][j] = 0.f;
        float m0 = MASKV, m1 = MASKV, l0 = 0.f, l1 = 0.f;

        const int r0 = wr * 16 + g4, r1 = r0 + 8;

        for (int kt = 0; kt <= qt; kt++) {
            CP_WAIT0();
            __syncthreads();
            const uint32_t kvb = sb + AKV0 + (uint32_t)((kt & 1) * KVBUF);

            // ---- S = Q K^T (2-term fp16: (qh+ql) x k_hi) ----
            float sacc[4][4];
#pragma unroll
            for (int nt = 0; nt < 4; nt++)
#pragma unroll
                for (int j = 0; j < 4; j++) sacc[nt][j] = 0.f;

#pragma unroll
            for (int ks = 0; ks < 8; ks++) {
                uint32_t qh[4], ql[4];
                {
                    int gq = ks * 2 + (lane >> 4);
                    uint32_t off = q_rb + (uint32_t)((gq ^ q_xr) << 4);
                    LDSM4(qh[0], qh[1], qh[2], qh[3], sb + AQH + off);
                    LDSM4(ql[0], ql[1], ql[2], ql[3], sb + AQL + off);
                }
                const int gq = ks * 2 + b3;
                const uint32_t csw = (uint32_t)((gq ^ xr7) << 4);
#pragma unroll
                for (int p = 0; p < 2; p++) {
                    const uint32_t off =
                        (uint32_t)((wh * 32 + p * 16 + rk) * 256) + csw;
                    uint32_t h0, h1, h2, h3;
                    LDSM4(h0, h1, h2, h3, kvb + off);
                    uint32_t bh0[2] = {h0, h1}, bh1[2] = {h2, h3};
                    MMA16816H(sacc[2 * p],     qh, bh0);
                    MMA16816H(sacc[2 * p],     ql, bh0);
                    MMA16816H(sacc[2 * p + 1], qh, bh1);
                    MMA16816H(sacc[2 * p + 1], ql, bh1);
                }
            }

            // ---- exp2-domain scale + causal mask ----
#pragma unroll
            for (int nt = 0; nt < 4; nt++)
#pragma unroll
                for (int j = 0; j < 4; j++) sacc[nt][j] *= SCALE2;
            if (kt == qt) {
#pragma unroll
                for (int nt = 0; nt < 4; nt++) {
                    const int c0 = wh * 32 + nt * 8 + tig * 2, c1 = c0 + 1;
                    if (c0 > r0) sacc[nt][0] = MASKV;
                    if (c1 > r0) sacc[nt][1] = MASKV;
                    if (c0 > r1) sacc[nt][2] = MASKV;
                    if (c1 > r1) sacc[nt][3] = MASKV;
                }
            }

            float rm0 = MASKV, rm1 = MASKV;
#pragma unroll
            for (int nt = 0; nt < 4; nt++) {
                rm0 = fmaxf(rm0, fmaxf(sacc[nt][0], sacc[nt][1]));
                rm1 = fmaxf(rm1, fmaxf(sacc[nt][2], sacc[nt][3]));
            }
            rm0 = fmaxf(rm0, __shfl_xor_sync(0xffffffffu, rm0, 1));
            rm0 = fmaxf(rm0, __shfl_xor_sync(0xffffffffu, rm0, 2));
            rm1 = fmaxf(rm1, __shfl_xor_sync(0xffffffffu, rm1, 1));
            rm1 = fmaxf(rm1, __shfl_xor_sync(0xffffffffu, rm1, 2));
            if (tig == 0) {
                mPart[wh * 64 + r0] = rm0;
                mPart[wh * 64 + r1] = rm1;
            }

            float rs0 = 0.f, rs1 = 0.f;
#pragma unroll
            for (int nt = 0; nt < 4; nt++) {
                float p0 = exp2f(sacc[nt][0] - rm0);
                float p1 = exp2f(sacc[nt][1] - rm0);
                float p2 = exp2f(sacc[nt][2] - rm1);
                float p3 = exp2f(sacc[nt][3] - rm1);
                sacc[nt][0] = p0; sacc[nt][1] = p1;
                sacc[nt][2] = p2; sacc[nt][3] = p3;
                rs0 += p0 + p1; rs1 += p2 + p3;
            }
            rs0 += __shfl_xor_sync(0xffffffffu, rs0, 1);
            rs0 += __shfl_xor_sync(0xffffffffu, rs0, 2);
            rs1 += __shfl_xor_sync(0xffffffffu, rs1, 1);
            rs1 += __shfl_xor_sync(0xffffffffu, rs1, 2);
            if (tig == 0) {
                sPart[wh * 64 + r0] = rs0;
                sPart[wh * 64 + r1] = rs1;
            }
            __syncthreads();          // stat exchange barrier

            // prefetch next KV AFTER exchange (all warps done with other buf)
            if (kt < qt) {
                kv_issue256(sb + AKV0 + (uint32_t)(((kt + 1) & 1) * KVBUF),
                            batchbase + (size_t)(kt + 1) * 64 * H_, tid);
                CP_COMMIT();
            }

            const float rmA0 = mPart[r0], rmB0 = mPart[64 + r0];
            const float rmA1 = mPart[r1], rmB1 = mPart[64 + r1];
            const float mn0 = fmaxf(m0, fmaxf(rmA0, rmB0));
            const float mn1 = fmaxf(m1, fmaxf(rmA1, rmB1));
            const float corr0 = exp2f(m0 - mn0), corr1 = exp2f(m1 - mn1);
            l0 = l0 * corr0 + sPart[r0]      * exp2f(rmA0 - mn0)
                            + sPart[64 + r0] * exp2f(rmB0 - mn0);
            l1 = l1 * corr1 + sPart[r1]      * exp2f(rmA1 - mn1)
                            + sPart[64 + r1] * exp2f(rmB1 - mn1);
            m0 = mn0; m1 = mn1;
            const float fac0 = exp2f(rm0 - mn0);
            const float fac1 = exp2f(rm1 - mn1);

#pragma unroll
            for (int t = 0; t < 16; t++) {
                oacc[t][0] *= corr0; oacc[t][1] *= corr0;
                oacc[t][2] *= corr1; oacc[t][3] *= corr1;
            }

            // ---- P fp16 hi/lo fragments (rescale folded) ----
            uint32_t ph[2][4], pl[2][4];
#pragma unroll
            for (int c = 0; c < 2; c++) {
#pragma unroll
                for (int half = 0; half < 2; half++) {
                    const int nt = 2 * c + half;
                    float a0 = sacc[nt][0] * fac0, a1 = sacc[nt][1] * fac0;
                    float a2 = sacc[nt][2] * fac1, a3 = sacc[nt][3] * fac1;
                    __half h0 = __float2half_rn(a0);
                    __half h1 = __float2half_rn(a1);
                    __half h2 = __float2half_rn(a2);
                    __half h3 = __float2half_rn(a3);
                    ph[c][2 * half] =
                        (uint32_t)__half_as_ushort(h0) |
                        ((uint32_t)__half_as_ushort(h1) << 16);
                    ph[c][2 * half + 1] =
                        (uint32_t)__half_as_ushort(h2) |
                        ((uint32_t)__half_as_ushort(h3) << 16);
                    pl[c][2 * half] =
                        pack_h2(a0 - __half2float(h0), a1 - __half2float(h1));
                    pl[c][2 * half + 1] =
                        pack_h2(a2 - __half2float(h2), a3 - __half2float(h3));
                }
            }

            // ---- O += (P_hi + P_lo) x V_hi ----
#pragma unroll
            for (int c = 0; c < 2; c++) {
                const uint32_t roff = (uint32_t)(((wh * 2 + c) * 16 + rk) * 256);
#pragma unroll
                for (int jp = 0; jp < 8; jp++) {
                    const int gq = jp * 2 + b3;
                    const uint32_t off = roff + (uint32_t)((gq ^ xr7) << 4);
                    uint32_t t0, t1, t2, t3;
                    LDSM4T(t0, t1, t2, t3, kvb + 16384 + off);
                    uint32_t vh0[2] = {t0, t2}, vh1[2] = {t1, t3};
                    MMA16816H(oacc[2 * jp],     ph[c], vh0);
                    MMA16816H(oacc[2 * jp],     pl[c], vh0);
                    MMA16816H(oacc[2 * jp + 1], ph[c], vh1);
                    MMA16816H(oacc[2 * jp + 1], pl[c], vh1);
                }
            }
            // no end barrier: next write into this buf is gated by the
            // NEXT tile's exchange barrier.
        }

        // ---- merge partial O between col-half partners, then store ----
        __syncthreads();
        if (wh == 1) {
            float* buf = (float*)(smA + AKV0 + wr * 8192);
#pragma unroll
            for (int t = 0; t < 16; t++) {
                const int col = t * 8 + tig * 2;
                *(float2*)&buf[g4 * 128 + col] =
                    make_float2(oacc[t][0], oacc[t][1]);
                *(float2*)&buf[(g4 + 8) * 128 + col] =
                    make_float2(oacc[t][2], oacc[t][3]);
            }
        }
        __syncthreads();
        if (wh == 0) {
            const float* buf = (const float*)(smA + AKV0 + wr * 8192);
            const float inv0 = 1.f / l0, inv1 = 1.f / l1;
#pragma unroll
            for (int t = 0; t < 16; t++) {
                const int col = t * 8 + tig * 2;
                float2 p0 = *(const float2*)&buf[g4 * 128 + col];
                float2 p1 = *(const float2*)&buf[(g4 + 8) * 128 + col];
                *(float2*)(out + qbase + (size_t)r0 * H_ + col) =
                    make_float2((oacc[t][0] + p0.x) * inv0,
                                (oacc[t][1] + p0.y) * inv0);
                *(float2*)(out + qbase + (size_t)r1 * H_ + col) =
                    make_float2((oacc[t][2] + p1.x) * inv1,
                                (oacc[t][3] + p1.y) * inv1);
            }
        }
    }
}

// ---------------------------------------------------------------------------
extern "C" void kernel_launch(void* const* d_in, const int* in_sizes, int n_in,
                              void* d_out, int out_size)
{
    const float* x  = (const float*)d_in[0];
    const float* Wq = (const float*)d_in[1];
    const float* Wk = (const float*)d_in[2];
    const float* Wv = (const float*)d_in[3];
    float* out = (float*)d_out;

    prep_kernel<<<4480, 256>>>(x, Wq, Wk, Wv);

    cudaFuncSetAttribute(qkv_mma_kernel,
                         cudaFuncAttributeMaxDynamicSharedMemorySize, QK_SMEM);
    qkv_mma_kernel<<<dim3(6, 128), 256, QK_SMEM>>>();

    cudaFuncSetAttribute(attn_mma_kernel,
                         cudaFuncAttributeMaxDynamicSharedMemorySize, ATT_SMEM);
    attn_mma_kernel<<<dim3(16, 8), 256, ATT_SMEM>>>(out);
}

// round 13
// speedup vs baseline: 1.4241x; 1.1466x over previous
#include <cuda_runtime.h>
#include <cuda_bf16.h>
#include <cuda_fp16.h>
#include <math.h>
#include <stdint.h>

#define B_ 8
#define T_ 2048
#define D_ 1024
#define H_ 128
#define SCALE2 0.12751763226289247f   // log2(e)/sqrt(128)
#define MASKV  (-1e30f)

__device__ __forceinline__ uint32_t smem_u32(const void* p) {
    uint32_t a;
    asm("{ .reg .u64 t; cvta.to.shared.u64 t, %1; cvt.u32.u64 %0, t; }"
        : "=r"(a) : "l"(p));
    return a;
}
__device__ __forceinline__ uint32_t pack_h2(float a, float b) {
    __half2 t = __floats2half2_rn(a, b);
    return *reinterpret_cast<uint32_t*>(&t);
}

#define CP16(dst, src) \
    asm volatile("cp.async.cg.shared.global [%0], [%1], 16;" \
                 :: "r"(dst), "l"(src) : "memory")
#define CP_COMMIT() asm volatile("cp.async.commit_group;" ::: "memory")
#define CP_WAIT0()  asm volatile("cp.async.wait_group 0;" ::: "memory")
#define CP_WAIT1()  asm volatile("cp.async.wait_group 1;" ::: "memory")

#define LDSM4(r0, r1, r2, r3, addr) \
    asm volatile("ldmatrix.sync.aligned.m8n8.x4.shared.b16 {%0,%1,%2,%3}, [%4];" \
                 : "=r"(r0), "=r"(r1), "=r"(r2), "=r"(r3) : "r"(addr))
#define LDSM4T(r0, r1, r2, r3, addr) \
    asm volatile("ldmatrix.sync.aligned.m8n8.x4.trans.shared.b16 {%0,%1,%2,%3}, [%4];" \
                 : "=r"(r0), "=r"(r1), "=r"(r2), "=r"(r3) : "r"(addr))

#define MMA16816H(d, a, b) \
    asm volatile("mma.sync.aligned.m16n8k16.row.col.f32.f16.f16.f32 " \
                 "{%0,%1,%2,%3},{%4,%5,%6,%7},{%8,%9},{%0,%1,%2,%3};" \
                 : "+f"((d)[0]), "+f"((d)[1]), "+f"((d)[2]), "+f"((d)[3]) \
                 : "r"((a)[0]), "r"((a)[1]), "r"((a)[2]), "r"((a)[3]), \
                   "r"((b)[0]), "r"((b)[1]))

// ---- device scratch (all fp16 now) ----
__device__ __half g_q_hi[(size_t)B_ * T_ * H_];
__device__ __half g_q_lo[(size_t)B_ * T_ * H_];
__device__ __half g_k_hi[(size_t)B_ * T_ * H_];
__device__ __half g_v_hi[(size_t)B_ * T_ * H_];
__device__ __half g_Wb_hi[384 * 1024];
__device__ __half g_x_hi[(size_t)B_ * T_ * D_];
__device__ __half g_x_lo[(size_t)B_ * T_ * D_];

// ---------------------------------------------------------------------------
// Fused prep, MLP=4: X -> fp16 hi/lo; Wcat -> fp16 hi only.
// ---------------------------------------------------------------------------
__global__ __launch_bounds__(256) void prep_kernel(
    const float* __restrict__ x,
    const float* __restrict__ Wq,
    const float* __restrict__ Wk,
    const float* __restrict__ Wv)
{
    if (blockIdx.x < 4096) {
        const size_t base = (size_t)blockIdx.x * 1024 + threadIdx.x;
        float4 f[4];
#pragma unroll
        for (int k = 0; k < 4; k++) f[k] = ((const float4*)x)[base + k * 256];
#pragma unroll
        for (int k = 0; k < 4; k++) {
            __half h0 = __float2half_rn(f[k].x);
            __half h1 = __float2half_rn(f[k].y);
            __half h2 = __float2half_rn(f[k].z);
            __half h3 = __float2half_rn(f[k].w);
            uint2 hv, lv;
            hv.x = (uint32_t)__half_as_ushort(h0) |
                   ((uint32_t)__half_as_ushort(h1) << 16);
            hv.y = (uint32_t)__half_as_ushort(h2) |
                   ((uint32_t)__half_as_ushort(h3) << 16);
            lv.x = pack_h2(f[k].x - __half2float(h0), f[k].y - __half2float(h1));
            lv.y = pack_h2(f[k].z - __half2float(h2), f[k].w - __half2float(h3));
            ((uint2*)g_x_hi)[base + k * 256] = hv;
            ((uint2*)g_x_lo)[base + k * 256] = lv;
        }
    } else {
        const int n = blockIdx.x - 4096;
        const float* W = (n < 128) ? Wq : (n < 256 ? Wk : Wv);
        const int h = n & 127;
        for (int k = threadIdx.x; k < 1024; k += 256) {
            g_Wb_hi[(size_t)n * 1024 + k] = __float2half_rn(W[(size_t)k * H_ + h]);
        }
    }
}

// ---------------------------------------------------------------------------
// QKV GEMM: fp16 2-term ((xh+xl) x w_hi). CTA 128x64, 256 thr, warps 4x2,
// 2 CTAs/SM. Stage: AH 0 (16K) | AL 16K (16K) | BH 32K (8K) = 40KB.
// ---------------------------------------------------------------------------
#define QSTG 40960
#define QK_SMEM (2 * QSTG)

__device__ __forceinline__ void qkv_issue(uint32_t dstbase, int m0, int n0,
                                          int k0, int tid)
{
#pragma unroll
    for (int i = 0; i < 4; i++) {
        int idx = i * 256 + tid;
        int r = idx >> 3, g = idx & 7;
        uint32_t off = (uint32_t)(r * 128 + ((g ^ (r & 7)) << 4));
        const size_t ax = (size_t)(m0 + r) * D_ + k0 + g * 8;
        CP16(dstbase + off,         g_x_hi + ax);
        CP16(dstbase + 16384 + off, g_x_lo + ax);
    }
#pragma unroll
    for (int i = 0; i < 2; i++) {
        int idx = i * 256 + tid;
        int r = idx >> 3, g = idx & 7;
        uint32_t off = (uint32_t)(r * 128 + ((g ^ (r & 7)) << 4));
        const size_t bx = (size_t)(n0 + r) * D_ + k0 + g * 8;
        CP16(dstbase + 32768 + off, g_Wb_hi + bx);
    }
}

__global__ __launch_bounds__(256, 2) void qkv_mma_kernel()
{
    extern __shared__ char smq[];
    const uint32_t sb = smem_u32(smq);
    const int tid  = threadIdx.x;
    const int lane = tid & 31, warp = tid >> 5;
    const int wm = warp >> 1, wn = warp & 1;
    const int m0 = blockIdx.y * 128;
    const int n0 = blockIdx.x * 64;

    float acc[2][4][4];
#pragma unroll
    for (int mt = 0; mt < 2; mt++)
#pragma unroll
        for (int nt = 0; nt < 4; nt++)
#pragma unroll
            for (int j = 0; j < 4; j++) acc[mt][nt][j] = 0.f;

    uint32_t a_rb[2], a_xr[2];
#pragma unroll
    for (int mt = 0; mt < 2; mt++) {
        int rowA = wm * 32 + mt * 16 + (lane & 15);
        a_rb[mt] = (uint32_t)(rowA * 128);
        a_xr[mt] = (uint32_t)((rowA & 7) << 4);
    }
    const uint32_t a_cb = (uint32_t)((lane >> 4) * 16);
    uint32_t b_rb[2], b_xr[2];
#pragma unroll
    for (int p = 0; p < 2; p++) {
        int nB = wn * 32 + p * 16 + ((lane >> 4) << 3) + (lane & 7);
        b_rb[p] = (uint32_t)(nB * 128);
        b_xr[p] = (uint32_t)((nB & 7) << 4);
    }
    const uint32_t b_cb = (uint32_t)(((lane >> 3) & 1) * 16);

    qkv_issue(sb, m0, n0, 0, tid);
    CP_COMMIT();

    for (int kc = 0; kc < 16; kc++) {
        if (kc < 15) {
            qkv_issue(sb + (uint32_t)(((kc + 1) & 1) * QSTG),
                      m0, n0, (kc + 1) * 64, tid);
            CP_COMMIT();
            CP_WAIT1();
        } else {
            CP_WAIT0();
        }
        __syncthreads();

        const uint32_t bufb = sb + (uint32_t)((kc & 1) * QSTG);
#pragma unroll
        for (int ks = 0; ks < 4; ks++) {
            const uint32_t acol = (a_cb + ks * 32);
            const uint32_t bcol = (b_cb + ks * 32);
            uint32_t ah[2][4], al[2][4];
#pragma unroll
            for (int mt = 0; mt < 2; mt++) {
                LDSM4(ah[mt][0], ah[mt][1], ah[mt][2], ah[mt][3],
                      bufb + a_rb[mt] + (acol ^ a_xr[mt]));
                LDSM4(al[mt][0], al[mt][1], al[mt][2], al[mt][3],
                      bufb + 16384 + a_rb[mt] + (acol ^ a_xr[mt]));
            }
            uint32_t bh[4][2];
#pragma unroll
            for (int p = 0; p < 2; p++) {
                uint32_t r0, r1, r2, r3;
                LDSM4(r0, r1, r2, r3, bufb + 32768 + b_rb[p] + (bcol ^ b_xr[p]));
                bh[2 * p][0] = r0; bh[2 * p][1] = r1;
                bh[2 * p + 1][0] = r2; bh[2 * p + 1][1] = r3;
            }
#pragma unroll
            for (int mt = 0; mt < 2; mt++)
#pragma unroll
                for (int nt = 0; nt < 4; nt++) {
                    MMA16816H(acc[mt][nt], ah[mt], bh[nt]);
                    MMA16816H(acc[mt][nt], al[mt], bh[nt]);
                }
        }
        __syncthreads();
    }

    // ---- epilogue: fp16 outputs. Q: hi+lo, K/V: hi only. ----
    const int sel = n0 >> 7;
    __half* oh = (sel == 0) ? g_q_hi : (sel == 1 ? g_k_hi : g_v_hi);
    const int colbase = n0 & 127;
    const int g = lane >> 2, tig = lane & 3;
#pragma unroll
    for (int mt = 0; mt < 2; mt++) {
        const int row0 = m0 + wm * 32 + mt * 16 + g;
#pragma unroll
        for (int nt = 0; nt < 4; nt++) {
            const int col = colbase + wn * 32 + nt * 8 + tig * 2;
#pragma unroll
            for (int h = 0; h < 2; h++) {
                const int row = row0 + h * 8;
                float a0 = acc[mt][nt][2 * h], a1 = acc[mt][nt][2 * h + 1];
                __half h0 = __float2half_rn(a0);
                __half h1 = __float2half_rn(a1);
                uint32_t hv = (uint32_t)__half_as_ushort(h0) |
                              ((uint32_t)__half_as_ushort(h1) << 16);
                *(uint32_t*)(oh + (size_t)row * H_ + col) = hv;
                if (sel == 0) {
                    *(uint32_t*)(g_q_lo + (size_t)row * H_ + col) =
                        pack_h2(a0 - __half2float(h0), a1 - __half2float(h1));
                }
            }
        }
    }
}

// ---------------------------------------------------------------------------
// Flash attention (R12, unchanged): fp16 2-term, 256 threads,
// 4 row-groups x 2 col-halves, KV stage 32KB, 2 barriers/tile.
// ---------------------------------------------------------------------------
#define AQH 0
#define AQL 16384
#define AKV0 32768
#define KVBUF 32768
#define AEXM 98304
#define AEXS 98816
#define ATT_SMEM 99328

__device__ __forceinline__ void kv_issue256(uint32_t dstbase, size_t kbase, int tid)
{
#pragma unroll
    for (int i = 0; i < 4; i++) {
        int idx = i * 256 + tid;
        int r = idx >> 4, gq = idx & 15;
        uint32_t off = (uint32_t)(r * 256 + ((gq ^ (r & 7)) << 4));
        const size_t ge = kbase + (size_t)r * 128 + gq * 8;
        CP16(dstbase + off,         g_k_hi + ge);
        CP16(dstbase + 16384 + off, g_v_hi + ge);
    }
}

__global__ __launch_bounds__(256, 1) void attn_mma_kernel(float* __restrict__ out)
{
    extern __shared__ char smA[];
    const uint32_t sb = smem_u32(smA);
    float* mPart = (float*)(smA + AEXM);
    float* sPart = (float*)(smA + AEXS);

    const int tid  = threadIdx.x;
    const int lane = tid & 31, warp = tid >> 5;
    const int wr = warp & 3;
    const int wh = warp >> 2;
    const int b    = blockIdx.y;
    const int g4   = lane >> 2, tig = lane & 3;
    const int b3   = (lane >> 3) & 1;
    const int rk   = ((lane >> 4) << 3) + (lane & 7);
    const int xr7  = lane & 7;

    const int qrow = wr * 16 + (lane & 15);
    const uint32_t q_rb = (uint32_t)(qrow * 256);
    const uint32_t q_xr = (uint32_t)((qrow & 7));

    for (int pass = 0; pass < 2; pass++) {
        const int qt = pass ? (31 - (int)blockIdx.x) : (int)blockIdx.x;
        const size_t qbase = ((size_t)b * T_ + (size_t)qt * 64) * H_;
        const size_t batchbase = (size_t)b * T_ * H_;

        __syncthreads();
        kv_issue256(sb + AKV0, batchbase, tid);
        CP_COMMIT();

#pragma unroll
        for (int i = 0; i < 4; i++) {
            int idx = i * 256 + tid;
            int r = idx >> 4, gq = idx & 15;
            uint32_t off = (uint32_t)(r * 256 + ((gq ^ (r & 7)) << 4));
            *(uint4*)(smA + AQH + off) = *(const uint4*)(g_q_hi + qbase + r * 128 + gq * 8);
            *(uint4*)(smA + AQL + off) = *(const uint4*)(g_q_lo + qbase + r * 128 + gq * 8);
        }

        float oacc[16][4];
#pragma unroll
        for (int t = 0; t < 16; t++)
#pragma unroll
            for (int j = 0; j < 4; j++) oacc[t][j] = 0.f;
        float m0 = MASKV, m1 = MASKV, l0 = 0.f, l1 = 0.f;

        const int r0 = wr * 16 + g4, r1 = r0 + 8;

        for (int kt = 0; kt <= qt; kt++) {
            CP_WAIT0();
            __syncthreads();
            const uint32_t kvb = sb + AKV0 + (uint32_t)((kt & 1) * KVBUF);

            float sacc[4][4];
#pragma unroll
            for (int nt = 0; nt < 4; nt++)
#pragma unroll
                for (int j = 0; j < 4; j++) sacc[nt][j] = 0.f;

#pragma unroll
            for (int ks = 0; ks < 8; ks++) {
                uint32_t qh[4], ql[4];
                {
                    int gq = ks * 2 + (lane >> 4);
                    uint32_t off = q_rb + (uint32_t)((gq ^ q_xr) << 4);
                    LDSM4(qh[0], qh[1], qh[2], qh[3], sb + AQH + off);
                    LDSM4(ql[0], ql[1], ql[2], ql[3], sb + AQL + off);
                }
                const int gq = ks * 2 + b3;
                const uint32_t csw = (uint32_t)((gq ^ xr7) << 4);
#pragma unroll
                for (int p = 0; p < 2; p++) {
                    const uint32_t off =
                        (uint32_t)((wh * 32 + p * 16 + rk) * 256) + csw;
                    uint32_t h0, h1, h2, h3;
                    LDSM4(h0, h1, h2, h3, kvb + off);
                    uint32_t bh0[2] = {h0, h1}, bh1[2] = {h2, h3};
                    MMA16816H(sacc[2 * p],     qh, bh0);
                    MMA16816H(sacc[2 * p],     ql, bh0);
                    MMA16816H(sacc[2 * p + 1], qh, bh1);
                    MMA16816H(sacc[2 * p + 1], ql, bh1);
                }
            }

#pragma unroll
            for (int nt = 0; nt < 4; nt++)
#pragma unroll
                for (int j = 0; j < 4; j++) sacc[nt][j] *= SCALE2;
            if (kt == qt) {
#pragma unroll
                for (int nt = 0; nt < 4; nt++) {
                    const int c0 = wh * 32 + nt * 8 + tig * 2, c1 = c0 + 1;
                    if (c0 > r0) sacc[nt][0] = MASKV;
                    if (c1 > r0) sacc[nt][1] = MASKV;
                    if (c0 > r1) sacc[nt][2] = MASKV;
                    if (c1 > r1) sacc[nt][3] = MASKV;
                }
            }

            float rm0 = MASKV, rm1 = MASKV;
#pragma unroll
            for (int nt = 0; nt < 4; nt++) {
                rm0 = fmaxf(rm0, fmaxf(sacc[nt][0], sacc[nt][1]));
                rm1 = fmaxf(rm1, fmaxf(sacc[nt][2], sacc[nt][3]));
            }
            rm0 = fmaxf(rm0, __shfl_xor_sync(0xffffffffu, rm0, 1));
            rm0 = fmaxf(rm0, __shfl_xor_sync(0xffffffffu, rm0, 2));
            rm1 = fmaxf(rm1, __shfl_xor_sync(0xffffffffu, rm1, 1));
            rm1 = fmaxf(rm1, __shfl_xor_sync(0xffffffffu, rm1, 2));
            if (tig == 0) {
                mPart[wh * 64 + r0] = rm0;
                mPart[wh * 64 + r1] = rm1;
            }

            float rs0 = 0.f, rs1 = 0.f;
#pragma unroll
            for (int nt = 0; nt < 4; nt++) {
                float p0 = exp2f(sacc[nt][0] - rm0);
                float p1 = exp2f(sacc[nt][1] - rm0);
                float p2 = exp2f(sacc[nt][2] - rm1);
                float p3 = exp2f(sacc[nt][3] - rm1);
                sacc[nt][0] = p0; sacc[nt][1] = p1;
                sacc[nt][2] = p2; sacc[nt][3] = p3;
                rs0 += p0 + p1; rs1 += p2 + p3;
            }
            rs0 += __shfl_xor_sync(0xffffffffu, rs0, 1);
            rs0 += __shfl_xor_sync(0xffffffffu, rs0, 2);
            rs1 += __shfl_xor_sync(0xffffffffu, rs1, 1);
            rs1 += __shfl_xor_sync(0xffffffffu, rs1, 2);
            if (tig == 0) {
                sPart[wh * 64 + r0] = rs0;
                sPart[wh * 64 + r1] = rs1;
            }
            __syncthreads();

            if (kt < qt) {
                kv_issue256(sb + AKV0 + (uint32_t)(((kt + 1) & 1) * KVBUF),
                            batchbase + (size_t)(kt + 1) * 64 * H_, tid);
                CP_COMMIT();
            }

            const float rmA0 = mPart[r0], rmB0 = mPart[64 + r0];
            const float rmA1 = mPart[r1], rmB1 = mPart[64 + r1];
            const float mn0 = fmaxf(m0, fmaxf(rmA0, rmB0));
            const float mn1 = fmaxf(m1, fmaxf(rmA1, rmB1));
            const float corr0 = exp2f(m0 - mn0), corr1 = exp2f(m1 - mn1);
            l0 = l0 * corr0 + sPart[r0]      * exp2f(rmA0 - mn0)
                            + sPart[64 + r0] * exp2f(rmB0 - mn0);
            l1 = l1 * corr1 + sPart[r1]      * exp2f(rmA1 - mn1)
                            + sPart[64 + r1] * exp2f(rmB1 - mn1);
            m0 = mn0; m1 = mn1;
            const float fac0 = exp2f(rm0 - mn0);
            const float fac1 = exp2f(rm1 - mn1);

#pragma unroll
            for (int t = 0; t < 16; t++) {
                oacc[t][0] *= corr0; oacc[t][1] *= corr0;
                oacc[t][2] *= corr1; oacc[t][3] *= corr1;
            }

            uint32_t ph[2][4], pl[2][4];
#pragma unroll
            for (int c = 0; c < 2; c++) {
#pragma unroll
                for (int half = 0; half < 2; half++) {
                    const int nt = 2 * c + half;
                    float a0 = sacc[nt][0] * fac0, a1 = sacc[nt][1] * fac0;
                    float a2 = sacc[nt][2] * fac1, a3 = sacc[nt][3] * fac1;
                    __half h0 = __float2half_rn(a0);
                    __half h1 = __float2half_rn(a1);
                    __half h2 = __float2half_rn(a2);
                    __half h3 = __float2half_rn(a3);
                    ph[c][2 * half] =
                        (uint32_t)__half_as_ushort(h0) |
                        ((uint32_t)__half_as_ushort(h1) << 16);
                    ph[c][2 * half + 1] =
                        (uint32_t)__half_as_ushort(h2) |
                        ((uint32_t)__half_as_ushort(h3) << 16);
                    pl[c][2 * half] =
                        pack_h2(a0 - __half2float(h0), a1 - __half2float(h1));
                    pl[c][2 * half + 1] =
                        pack_h2(a2 - __half2float(h2), a3 - __half2float(h3));
                }
            }

#pragma unroll
            for (int c = 0; c < 2; c++) {
                const uint32_t roff = (uint32_t)(((wh * 2 + c) * 16 + rk) * 256);
#pragma unroll
                for (int jp = 0; jp < 8; jp++) {
                    const int gq = jp * 2 + b3;
                    const uint32_t off = roff + (uint32_t)((gq ^ xr7) << 4);
                    uint32_t t0, t1, t2, t3;
                    LDSM4T(t0, t1, t2, t3, kvb + 16384 + off);
                    uint32_t vh0[2] = {t0, t2}, vh1[2] = {t1, t3};
                    MMA16816H(oacc[2 * jp],     ph[c], vh0);
                    MMA16816H(oacc[2 * jp],     pl[c], vh0);
                    MMA16816H(oacc[2 * jp + 1], ph[c], vh1);
                    MMA16816H(oacc[2 * jp + 1], pl[c], vh1);
                }
            }
        }

        __syncthreads();
        if (wh == 1) {
            float* buf = (float*)(smA + AKV0 + wr * 8192);
#pragma unroll
            for (int t = 0; t < 16; t++) {
                const int col = t * 8 + tig * 2;
                *(float2*)&buf[g4 * 128 + col] =
                    make_float2(oacc[t][0], oacc[t][1]);
                *(float2*)&buf[(g4 + 8) * 128 + col] =
                    make_float2(oacc[t][2], oacc[t][3]);
            }
        }
        __syncthreads();
        if (wh == 0) {
            const float* buf = (const float*)(smA + AKV0 + wr * 8192);
            const float inv0 = 1.f / l0, inv1 = 1.f / l1;
#pragma unroll
            for (int t = 0; t < 16; t++) {
                const int col = t * 8 + tig * 2;
                float2 p0 = *(const float2*)&buf[g4 * 128 + col];
                float2 p1 = *(const float2*)&buf[(g4 + 8) * 128 + col];
                *(float2*)(out + qbase + (size_t)r0 * H_ + col) =
                    make_float2((oacc[t][0] + p0.x) * inv0,
                                (oacc[t][1] + p0.y) * inv0);
                *(float2*)(out + qbase + (size_t)r1 * H_ + col) =
                    make_float2((oacc[t][2] + p1.x) * inv1,
                                (oacc[t][3] + p1.y) * inv1);
            }
        }
    }
}

// ---------------------------------------------------------------------------
extern "C" void kernel_launch(void* const* d_in, const int* in_sizes, int n_in,
                              void* d_out, int out_size)
{
    const float* x  = (const float*)d_in[0];
    const float* Wq = (const float*)d_in[1];
    const float* Wk = (const float*)d_in[2];
    const float* Wv = (const float*)d_in[3];
    float* out = (float*)d_out;

    prep_kernel<<<4480, 256>>>(x, Wq, Wk, Wv);

    cudaFuncSetAttribute(qkv_mma_kernel,
                         cudaFuncAttributeMaxDynamicSharedMemorySize, QK_SMEM);
    qkv_mma_kernel<<<dim3(6, 128), 256, QK_SMEM>>>();

    cudaFuncSetAttribute(attn_mma_kernel,
                         cudaFuncAttributeMaxDynamicSharedMemorySize, ATT_SMEM);
    attn_mma_kernel<<<dim3(16, 8), 256, ATT_SMEM>>>(out);
}